// round 3
// baseline (speedup 1.0000x reference)
#include <cuda_runtime.h>
#include <math.h>

#define NN 50000
#define EE 400000
#define EPP 40000
#define HH 128

// ---------------- scratch (device globals; no runtime allocation) ------------
__device__ __align__(16) float    g_x[(size_t)NN*HH];
__device__ __align__(16) float    g_n1[(size_t)NN*HH];
__device__ __align__(16) float    g_n2[(size_t)NN*HH];
__device__ __align__(16) float    g_s1[(size_t)NN*HH];
__device__ __align__(16) float    g_s2[(size_t)NN*HH];
__device__ __align__(16) unsigned g_mn[(size_t)NN*HH];
__device__ __align__(16) unsigned g_mx[(size_t)NN*HH];
__device__ __align__(16) float    g_agg[(size_t)NN*4*HH];
__device__ __align__(16) float    g_ea[(size_t)EE*HH];
__device__ __align__(16) float    g_eb1[(size_t)EE*HH];
__device__ __align__(16) float    g_eb2[(size_t)EE*HH];
__device__ float g_deg[NN];
__device__ float g_amp[NN];
__device__ float g_att[NN];
__device__ float g_dinv[NN];
__device__ float g_has[NN];
__device__ __align__(16) float g_W3[HH*HH];
__device__ __align__(16) float g_Wfold[13*HH*HH];
__device__ __align__(16) float g_bias1[HH];
__device__ __align__(16) float g_bias2[HH];
__device__ float g_bns[HH];
__device__ float g_bnq[HH];

// ---------------- helpers ----------------------------------------------------
__device__ __forceinline__ unsigned fenc(float f) {
    unsigned u = __float_as_uint(f);
    return (u & 0x80000000u) ? ~u : (u | 0x80000000u);
}
__device__ __forceinline__ float fdec(unsigned u) {
    return __uint_as_float((u & 0x80000000u) ? (u ^ 0x80000000u) : ~u);
}

// ---------------- generic fp32 GEMM: C[M,128] = alpha*A[M,K]@B[K,128] + bscale*bias + beta*C
__global__ __launch_bounds__(256) void k_gemm(
    const float* __restrict__ A, const float* __restrict__ B,
    const float* __restrict__ bias, float* __restrict__ C,
    int M, int K, float alpha, float beta, float bscale)
{
    __shared__ float As[64][16];
    __shared__ float Bs[16][128];
    const int t = threadIdx.x;
    const int m0 = blockIdx.x * 64;
    const int lane = t & 31;
    const int wrow = (t >> 5) * 8;
    const int col0 = lane * 4;
    const int ar = t >> 2;
    const int ak = (t & 3) * 4;
    const int br = t >> 4;
    const int bc = (t & 15) * 8;

    float acc[8][4];
#pragma unroll
    for (int i = 0; i < 8; i++) { acc[i][0]=0.f; acc[i][1]=0.f; acc[i][2]=0.f; acc[i][3]=0.f; }

    for (int k0 = 0; k0 < K; k0 += 16) {
        float4 av = make_float4(0.f,0.f,0.f,0.f);
        int grow = m0 + ar;
        if (grow < M) av = *(const float4*)(A + (size_t)grow * K + k0 + ak);
        *(float4*)&As[ar][ak] = av;
        *(float4*)&Bs[br][bc]     = *(const float4*)(B + (size_t)(k0 + br) * HH + bc);
        *(float4*)&Bs[br][bc + 4] = *(const float4*)(B + (size_t)(k0 + br) * HH + bc + 4);
        __syncthreads();
#pragma unroll
        for (int k = 0; k < 16; k++) {
            float4 b = *(const float4*)&Bs[k][col0];
#pragma unroll
            for (int i = 0; i < 8; i++) {
                float a = As[wrow + i][k];
                acc[i][0] = fmaf(a, b.x, acc[i][0]);
                acc[i][1] = fmaf(a, b.y, acc[i][1]);
                acc[i][2] = fmaf(a, b.z, acc[i][2]);
                acc[i][3] = fmaf(a, b.w, acc[i][3]);
            }
        }
        __syncthreads();
    }

    float4 bv = make_float4(0.f,0.f,0.f,0.f);
    if (bias) {
        bv = *(const float4*)(bias + col0);
        bv.x *= bscale; bv.y *= bscale; bv.z *= bscale; bv.w *= bscale;
    }
#pragma unroll
    for (int i = 0; i < 8; i++) {
        int r = m0 + wrow + i;
        if (r < M) {
            float4 o;
            o.x = acc[i][0] * alpha + bv.x;
            o.y = acc[i][1] * alpha + bv.y;
            o.z = acc[i][2] * alpha + bv.z;
            o.w = acc[i][3] * alpha + bv.w;
            if (beta != 0.f) {
                float4 c = *(const float4*)(C + (size_t)r * HH + col0);
                o.x += beta * c.x; o.y += beta * c.y; o.z += beta * c.z; o.w += beta * c.w;
            }
            *(float4*)(C + (size_t)r * HH + col0) = o;
        }
    }
}

// ---------------- fused post+lin GEMM: g_n1 = [x | agg | amp*agg | att*agg] @ g_Wfold + g_bias2
__global__ __launch_bounds__(256) void k_post()
{
    __shared__ float As[64][16];
    __shared__ float Bs[16][128];
    const int t = threadIdx.x;
    const int m0 = blockIdx.x * 64;
    const int lane = t & 31;
    const int wrow = (t >> 5) * 8;
    const int col0 = lane * 4;
    const int ar = t >> 2;
    const int ak = (t & 3) * 4;
    const int br = t >> 4;
    const int bc = (t & 15) * 8;
    const int K = 13 * HH; // 1664

    float acc[8][4];
#pragma unroll
    for (int i = 0; i < 8; i++) { acc[i][0]=0.f; acc[i][1]=0.f; acc[i][2]=0.f; acc[i][3]=0.f; }

    for (int k0 = 0; k0 < K; k0 += 16) {
        int grow = m0 + ar;
        float vals[4] = {0.f, 0.f, 0.f, 0.f};
        if (grow < NN) {
#pragma unroll
            for (int i = 0; i < 4; i++) {
                int kg = k0 + ak + i;
                float v;
                if (kg < HH) {
                    v = g_x[(size_t)grow * HH + kg];
                } else {
                    int kk = kg - HH;
                    int sec = kk >> 9;       // 0: agg, 1: amp*agg, 2: att*agg
                    int j = kk & 511;
                    v = g_agg[(size_t)grow * 512 + j];
                    if (sec == 1)      v *= g_amp[grow];
                    else if (sec == 2) v *= g_att[grow];
                }
                vals[i] = v;
            }
        }
        As[ar][ak + 0] = vals[0];
        As[ar][ak + 1] = vals[1];
        As[ar][ak + 2] = vals[2];
        As[ar][ak + 3] = vals[3];
        *(float4*)&Bs[br][bc]     = *(const float4*)(g_Wfold + (size_t)(k0 + br) * HH + bc);
        *(float4*)&Bs[br][bc + 4] = *(const float4*)(g_Wfold + (size_t)(k0 + br) * HH + bc + 4);
        __syncthreads();
#pragma unroll
        for (int k = 0; k < 16; k++) {
            float4 b = *(const float4*)&Bs[k][col0];
#pragma unroll
            for (int i = 0; i < 8; i++) {
                float a = As[wrow + i][k];
                acc[i][0] = fmaf(a, b.x, acc[i][0]);
                acc[i][1] = fmaf(a, b.y, acc[i][1]);
                acc[i][2] = fmaf(a, b.z, acc[i][2]);
                acc[i][3] = fmaf(a, b.w, acc[i][3]);
            }
        }
        __syncthreads();
    }

    float4 bv = *(const float4*)(g_bias2 + col0);
#pragma unroll
    for (int i = 0; i < 8; i++) {
        int r = m0 + wrow + i;
        if (r < NN) {
            float4 o;
            o.x = acc[i][0] + bv.x;
            o.y = acc[i][1] + bv.y;
            o.z = acc[i][2] + bv.z;
            o.w = acc[i][3] + bv.w;
            *(float4*)(g_n1 + (size_t)r * HH + col0) = o;
        }
    }
}

// ---------------- small kernels ----------------------------------------------
__global__ void k_zero(float* p, int n) {
    int i = blockIdx.x * blockDim.x + threadIdx.x;
    if (i < n) p[i] = 0.f;
}

__global__ void k_degacc(const int* __restrict__ dst) {
    int i = blockIdx.x * blockDim.x + threadIdx.x;
    if (i < EE) atomicAdd(&g_deg[dst[i]], 1.0f);
}

__global__ void k_nodestats(const float* __restrict__ adl_p) {
    int n = blockIdx.x * blockDim.x + threadIdx.x;
    if (n >= NN) return;
    float adl = __ldg(adl_p);
    float d = g_deg[n];
    float degc = fmaxf(d, 1.0f);
    float lg = logf(degc + 1.0f);
    g_amp[n]  = lg / adl;
    g_att[n]  = adl / lg;
    g_dinv[n] = 1.0f / degc;
    g_has[n]  = (d > 0.f) ? 1.f : 0.f;
}

// out[j] = b0[j] + sum_k v[k]*W[k*128+j]   (bias folding)
__global__ void k_vecmat(const float* __restrict__ v, const float* __restrict__ W,
                         const float* __restrict__ b0, float* __restrict__ out) {
    int j = threadIdx.x;
    float s = b0[j];
    for (int k = 0; k < HH; k++) s = fmaf(v[k], W[k * HH + j], s);
    out[j] = s;
}

__global__ void k_initagg() {
    int i = blockIdx.x * blockDim.x + threadIdx.x;
    if (i >= NN * HH) return;
    g_s1[i] = 0.f;
    g_s2[i] = 0.f;
    g_mn[i] = 0xFF800000u; // enc(+inf)
    g_mx[i] = 0x007FFFFFu; // enc(-inf)
}

// message + scatter-reduce: one warp per edge, 4 cols per lane
__global__ __launch_bounds__(256) void k_msg(const int* __restrict__ src, const int* __restrict__ dst) {
    int e = blockIdx.x * 8 + (threadIdx.x >> 5);
    int lane = threadIdx.x & 31;
    int c = lane * 4;
    int s = __ldg(src + e);
    int d = __ldg(dst + e);
    float4 a  = *(const float4*)(g_n1 + (size_t)d * HH + c);
    float4 b  = *(const float4*)(g_n2 + (size_t)s * HH + c);
    float4 w  = *(const float4*)(g_eb1 + (size_t)e * HH + c);
    float4 bb = *(const float4*)(g_bias1 + c);
    float h[4] = { a.x + b.x + w.x + bb.x, a.y + b.y + w.y + bb.y,
                   a.z + b.z + w.z + bb.z, a.w + b.w + w.w + bb.w };
    size_t base = (size_t)d * HH + c;
#pragma unroll
    for (int j = 0; j < 4; j++) {
        float hv = h[j];
        atomicAdd(&g_s1[base + j], hv);
        atomicAdd(&g_s2[base + j], hv * hv);
        unsigned u = fenc(hv);
        atomicMin(&g_mn[base + j], u);
        atomicMax(&g_mx[base + j], u);
    }
}

__global__ void k_makeagg() {
    int i = blockIdx.x * blockDim.x + threadIdx.x;
    if (i >= NN * HH) return;
    int n = i >> 7;
    int c = i & 127;
    float s1 = g_s1[i], s2 = g_s2[i];
    float dinv = g_dinv[n];
    float has = g_has[n];
    float mean = s1 * dinv;
    float var = fmaxf(s2 * dinv - mean * mean, 0.f);
    float sd = sqrtf(var + 1e-5f);
    float mn = (has > 0.f) ? fdec(g_mn[i]) : 0.f;
    float mx = (has > 0.f) ? fdec(g_mx[i]) : 0.f;
    size_t b = (size_t)n * 512;
    g_agg[b + c]       = mean;
    g_agg[b + 128 + c] = mn;
    g_agg[b + 256 + c] = mx;
    g_agg[b + 384 + c] = sd;
}

__global__ void k_bnzero() {
    int t = threadIdx.x;
    g_bns[t] = 0.f;
    g_bnq[t] = 0.f;
}

__global__ __launch_bounds__(256) void k_bnred() {
    __shared__ float sh[256], shq[256];
    int t = threadIdx.x;
    int col = t & 127;
    int half = t >> 7;
    float s = 0.f, q = 0.f;
    for (int row = blockIdx.x * 2 + half; row < NN; row += gridDim.x * 2) {
        float v = g_n1[(size_t)row * HH + col];
        s += v; q += v * v;
    }
    sh[t] = s; shq[t] = q;
    __syncthreads();
    if (half == 0) {
        atomicAdd(&g_bns[col], s + sh[t + 128]);
        atomicAdd(&g_bnq[col], q + shq[t + 128]);
    }
}

__global__ void k_bnapply(const float* __restrict__ gamma, const float* __restrict__ beta) {
    int i = blockIdx.x * blockDim.x + threadIdx.x;
    if (i >= NN * HH) return;
    int c = i & 127;
    const float invN = 1.0f / (float)NN;
    float mu = g_bns[c] * invN;
    float var = g_bnq[c] * invN - mu * mu;
    float v = g_n1[i];
    float bn = gamma[c] * (v - mu) * rsqrtf(var + 1e-5f) + beta[c];
    g_x[i] = (g_x[i] + fmaxf(bn, 0.f)) * 0.5f;
}

// upd = relu(xU1[src] + xU2[dst] + eaWu3[e] + b1) -> g_eb2
__global__ void k_upd(const int* __restrict__ src, const int* __restrict__ dst,
                      const float* __restrict__ b1) {
    int idx = blockIdx.x * blockDim.x + threadIdx.x; // float4 units; total EE*32
    int e = idx >> 5;
    int c = (idx & 31) * 4;
    int s = __ldg(src + e);
    int d = __ldg(dst + e);
    float4 a  = *(const float4*)(g_n1 + (size_t)s * HH + c);
    float4 b  = *(const float4*)(g_n2 + (size_t)d * HH + c);
    float4 w  = *(const float4*)(g_eb1 + (size_t)e * HH + c);
    float4 bb = *(const float4*)(b1 + c);
    float4 o;
    o.x = fmaxf(a.x + b.x + w.x + bb.x, 0.f);
    o.y = fmaxf(a.y + b.y + w.y + bb.y, 0.f);
    o.z = fmaxf(a.z + b.z + w.z + bb.z, 0.f);
    o.w = fmaxf(a.w + b.w + w.w + bb.w, 0.f);
    *(float4*)(g_eb2 + (size_t)e * HH + c) = o;
}

__global__ void k_copy(float* __restrict__ out) {
    int i = blockIdx.x * blockDim.x + threadIdx.x;
    if (i < NN * HH) out[i] = g_x[i];
}

// ---------------- host orchestration -----------------------------------------
extern "C" void kernel_launch(void* const* d_in, const int* in_sizes, int n_in,
                              void* d_out, int out_size) {
    const float* x_in   = (const float*)d_in[0];
    const int*   ei     = (const int*)d_in[1];
    const float* eattr  = (const float*)d_in[2];
    const float* pattr  = (const float*)d_in[4];
    const float* nattr  = (const float*)d_in[6];
    const float* adl    = (const float*)d_in[7];
    const float* node_w = (const float*)d_in[8];
    const float* node_b = (const float*)d_in[9];
    const float* edge_w = (const float*)d_in[10];
    const float* edge_b = (const float*)d_in[11];
    const float* eenc_w = (const float*)d_in[12];
    const float* eenc_b = (const float*)d_in[13];
    const float* pre_w  = (const float*)d_in[14];
    const float* pre_b  = (const float*)d_in[15];
    const float* post_w = (const float*)d_in[16];
    const float* post_b = (const float*)d_in[17];
    const float* lin_w  = (const float*)d_in[18];
    const float* lin_b  = (const float*)d_in[19];
    const float* ew1    = (const float*)d_in[20];
    const float* eb1v   = (const float*)d_in[21];
    const float* ew2    = (const float*)d_in[22];
    const float* eb2v   = (const float*)d_in[23];
    const float* bng    = (const float*)d_in[24];
    const float* bnb    = (const float*)d_in[25];
    float* out = (float*)d_out;

    float *p_x, *p_ea, *p_n1, *p_n2, *p_eb1, *p_eb2, *p_W3, *p_Wfold, *p_b1, *p_b2, *p_deg;
    cudaGetSymbolAddress((void**)&p_x, g_x);
    cudaGetSymbolAddress((void**)&p_ea, g_ea);
    cudaGetSymbolAddress((void**)&p_n1, g_n1);
    cudaGetSymbolAddress((void**)&p_n2, g_n2);
    cudaGetSymbolAddress((void**)&p_eb1, g_eb1);
    cudaGetSymbolAddress((void**)&p_eb2, g_eb2);
    cudaGetSymbolAddress((void**)&p_W3, g_W3);
    cudaGetSymbolAddress((void**)&p_Wfold, g_Wfold);
    cudaGetSymbolAddress((void**)&p_b1, g_bias1);
    cudaGetSymbolAddress((void**)&p_b2, g_bias2);
    cudaGetSymbolAddress((void**)&p_deg, g_deg);

    const int* src = ei;
    const int* dst = ei + EE;

    auto gemm = [](const float* A, const float* B, const float* bias, float* C,
                   int M, int K, float alpha, float beta, float bscale) {
        k_gemm<<<(M + 63) / 64, 256>>>(A, B, bias, C, M, K, alpha, beta, bscale);
    };

    // degree stats (fixed across layers)
    k_zero<<<(NN + 255) / 256, 256>>>(p_deg, NN);
    k_degacc<<<(EE + 255) / 256, 256>>>(dst);
    k_nodestats<<<(NN + 255) / 256, 256>>>(adl);

    // embeddings
    gemm(x_in, node_w, node_b, p_x, NN, 64, 1.f, 0.f, 1.f);
    gemm(eattr, edge_w, edge_b, p_ea, EE, 32, 1.f, 0.f, 1.f);
    gemm(pattr, edge_w, edge_b, out + (size_t)NN * HH, EPP, 32, 1.f, 0.f, 1.f);
    gemm(nattr, edge_w, edge_b, out + (size_t)NN * HH + (size_t)EPP * HH, EPP, 32, 1.f, 0.f, 1.f);

    for (int l = 0; l < 2; l++) {
        const float* preW = pre_w + (size_t)l * 384 * HH;
        const float* postW = post_w + (size_t)l * 1664 * HH;
        const float* linW = lin_w + (size_t)l * HH * HH;
        const float* e1W = ew1 + (size_t)l * 384 * HH;
        const float* e2W = ew2 + (size_t)l * HH * HH;

        // weight/bias folds
        gemm(eenc_w + (size_t)l * HH * HH, preW + 256 * HH, nullptr, p_W3, HH, HH, 1.f, 0.f, 0.f);
        k_vecmat<<<1, 128>>>(eenc_b + l * HH, preW + 256 * HH, pre_b + l * HH, p_b1);
        gemm(postW, linW, nullptr, p_Wfold, 13 * HH, HH, 1.f, 0.f, 0.f);
        k_vecmat<<<1, 128>>>(post_b + l * HH, linW, lin_b + l * HH, p_b2);

        // message projections
        gemm(p_x, preW, nullptr, p_n1, NN, HH, 1.f, 0.f, 0.f);            // x@P0 (dst side)
        gemm(p_x, preW + 128 * HH, nullptr, p_n2, NN, HH, 1.f, 0.f, 0.f); // x@P1 (src side)
        gemm(p_ea, p_W3, nullptr, p_eb1, EE, HH, 1.f, 0.f, 0.f);          // ea@(Ee@P2)

        // aggregate
        k_initagg<<<(NN * HH + 255) / 256, 256>>>();
        k_msg<<<EE / 8, 256>>>(src, dst);
        k_makeagg<<<(NN * HH + 255) / 256, 256>>>();

        // node update: fused post+lin, then BN + residual
        k_post<<<(NN + 63) / 64, 256>>>();
        k_bnzero<<<1, 128>>>();
        k_bnred<<<256, 256>>>();
        k_bnapply<<<(NN * HH + 255) / 256, 256>>>(bng + l * HH, bnb + l * HH);

        // edge update
        gemm(p_x, e1W, nullptr, p_n1, NN, HH, 1.f, 0.f, 0.f);            // x@U0 (src side)
        gemm(p_x, e1W + 128 * HH, nullptr, p_n2, NN, HH, 1.f, 0.f, 0.f); // x@U1 (dst side)
        gemm(p_ea, e1W + 256 * HH, nullptr, p_eb1, EE, HH, 1.f, 0.f, 0.f);
        k_upd<<<(EE * 32 + 255) / 256, 256>>>(src, dst, eb1v + l * HH);
        gemm(p_eb2, e2W, eb2v + l * HH, p_ea, EE, HH, 0.5f, 1.f, 0.5f);
    }

    k_copy<<<(NN * HH + 255) / 256, 256>>>(out);
}

// round 4
// speedup vs baseline: 1.6007x; 1.6007x over previous
#include <cuda_runtime.h>
#include <math.h>

#define NN 50000
#define EE 400000
#define EPP 40000
#define HH 128

// ---------------- scratch (device globals; no runtime allocation) ------------
__device__ __align__(16) float    g_x[(size_t)NN*HH];
__device__ __align__(16) float    g_n1[(size_t)NN*HH];
__device__ __align__(16) float    g_n2[(size_t)NN*HH];
__device__ __align__(16) float    g_s1[(size_t)NN*HH];
__device__ __align__(16) float    g_s2[(size_t)NN*HH];
__device__ __align__(16) unsigned g_mn[(size_t)NN*HH];
__device__ __align__(16) unsigned g_mx[(size_t)NN*HH];
__device__ __align__(16) float    g_agg[(size_t)NN*4*HH];
__device__ __align__(16) float    g_ea[(size_t)EE*HH];
__device__ __align__(16) float    g_eb1[(size_t)EE*HH];
__device__ __align__(16) float    g_eb2[(size_t)EE*HH];
__device__ float g_deg[NN];
__device__ float g_amp[NN];
__device__ float g_att[NN];
__device__ float g_dinv[NN];
__device__ float g_has[NN];
__device__ __align__(16) float g_W3[HH*HH];
__device__ __align__(16) float g_Wfold[13*HH*HH];
__device__ __align__(16) float g_bias1[HH];
__device__ __align__(16) float g_bias2[HH];
__device__ float g_bns[HH];
__device__ float g_bnq[HH];

// ---------------- helpers ----------------------------------------------------
__device__ __forceinline__ unsigned fenc(float f) {
    unsigned u = __float_as_uint(f);
    return (u & 0x80000000u) ? ~u : (u | 0x80000000u);
}
__device__ __forceinline__ float fdec(unsigned u) {
    return __uint_as_float((u & 0x80000000u) ? (u ^ 0x80000000u) : ~u);
}
__device__ __forceinline__ unsigned tf32r(float f) {
    unsigned u;
    asm("cvt.rna.tf32.f32 %0, %1;" : "=r"(u) : "f"(f));
    return u;
}
__device__ __forceinline__ uint4 tf32r4(float4 v) {
    uint4 o;
    o.x = tf32r(v.x); o.y = tf32r(v.y); o.z = tf32r(v.z); o.w = tf32r(v.w);
    return o;
}
__device__ __forceinline__ void mma_tf32(float* d, const unsigned* a, const unsigned* b) {
    asm volatile(
        "mma.sync.aligned.m16n8k8.row.col.f32.tf32.tf32.f32 "
        "{%0,%1,%2,%3}, {%4,%5,%6,%7}, {%8,%9}, {%0,%1,%2,%3};"
        : "+f"(d[0]), "+f"(d[1]), "+f"(d[2]), "+f"(d[3])
        : "r"(a[0]), "r"(a[1]), "r"(a[2]), "r"(a[3]), "r"(b[0]), "r"(b[1]));
}

// ---------------- tensor-core tf32 GEMM: C[M,128] = alpha*A[M,K]@B[K,128] + bscale*bias + beta*C
// block tile 128x128, 8 warps (4m x 2n), warp tile 32x64, BK=16
__global__ __launch_bounds__(256, 2) void k_gemm_tc(
    const float* __restrict__ A, const float* __restrict__ B,
    const float* __restrict__ bias, float* __restrict__ C,
    int M, int K, float alpha, float beta, float bscale)
{
    __shared__ unsigned As[128][20];   // pad: stride 20 -> conflict-free frag loads
    __shared__ unsigned Bs[16][136];   // pad: 136 % 32 == 8 -> conflict-free frag loads
    const int t = threadIdx.x;
    const int m0 = blockIdx.x * 128;
    const int warp = t >> 5, lane = t & 31;
    const int gid = lane >> 2, tq = lane & 3;
    const int wm = (warp >> 1) * 32, wn = (warp & 1) * 64;

    float acc[2][8][4];
#pragma unroll
    for (int mt = 0; mt < 2; mt++)
#pragma unroll
        for (int nt = 0; nt < 8; nt++)
#pragma unroll
            for (int i = 0; i < 4; i++) acc[mt][nt][i] = 0.f;

    for (int k0 = 0; k0 < K; k0 += 16) {
#pragma unroll
        for (int i = 0; i < 2; i++) {
            int v = t + 256 * i;
            int row = v >> 2, kq = (v & 3) * 4;
            float4 av = make_float4(0.f, 0.f, 0.f, 0.f);
            int gr = m0 + row;
            if (gr < M) av = *(const float4*)(A + (size_t)gr * K + k0 + kq);
            *(uint4*)&As[row][kq] = tf32r4(av);
            int kb = v >> 5, nq = (v & 31) * 4;
            float4 bv = *(const float4*)(B + (size_t)(k0 + kb) * HH + nq);
            *(uint4*)&Bs[kb][nq] = tf32r4(bv);
        }
        __syncthreads();
#pragma unroll
        for (int kk = 0; kk < 16; kk += 8) {
            unsigned af[2][4];
#pragma unroll
            for (int mt = 0; mt < 2; mt++) {
                int r = wm + mt * 16 + gid;
                af[mt][0] = As[r][kk + tq];
                af[mt][1] = As[r + 8][kk + tq];
                af[mt][2] = As[r][kk + tq + 4];
                af[mt][3] = As[r + 8][kk + tq + 4];
            }
#pragma unroll
            for (int nt = 0; nt < 8; nt++) {
                unsigned bf[2];
                bf[0] = Bs[kk + tq][wn + nt * 8 + gid];
                bf[1] = Bs[kk + tq + 4][wn + nt * 8 + gid];
                mma_tf32(acc[0][nt], af[0], bf);
                mma_tf32(acc[1][nt], af[1], bf);
            }
        }
        __syncthreads();
    }

#pragma unroll
    for (int nt = 0; nt < 8; nt++) {
        int col = wn + nt * 8 + tq * 2;
        float bx = 0.f, by = 0.f;
        if (bias) { bx = bias[col] * bscale; by = bias[col + 1] * bscale; }
#pragma unroll
        for (int mt = 0; mt < 2; mt++) {
            int r0 = m0 + wm + mt * 16 + gid;
            int r1 = r0 + 8;
            if (r0 < M) {
                float2 o;
                o.x = acc[mt][nt][0] * alpha + bx;
                o.y = acc[mt][nt][1] * alpha + by;
                if (beta != 0.f) {
                    float2 c = *(const float2*)(C + (size_t)r0 * HH + col);
                    o.x += beta * c.x; o.y += beta * c.y;
                }
                *(float2*)(C + (size_t)r0 * HH + col) = o;
            }
            if (r1 < M) {
                float2 o;
                o.x = acc[mt][nt][2] * alpha + bx;
                o.y = acc[mt][nt][3] * alpha + by;
                if (beta != 0.f) {
                    float2 c = *(const float2*)(C + (size_t)r1 * HH + col);
                    o.x += beta * c.x; o.y += beta * c.y;
                }
                *(float2*)(C + (size_t)r1 * HH + col) = o;
            }
        }
    }
}

// ---------------- fused post+lin on tensor cores:
// g_n1 = [x | agg | amp*agg | att*agg] @ g_Wfold + g_bias2   (K = 1664)
__global__ __launch_bounds__(256, 2) void k_post_tc()
{
    __shared__ unsigned As[128][20];
    __shared__ unsigned Bs[16][136];
    const int t = threadIdx.x;
    const int m0 = blockIdx.x * 128;
    const int warp = t >> 5, lane = t & 31;
    const int gid = lane >> 2, tq = lane & 3;
    const int wm = (warp >> 1) * 32, wn = (warp & 1) * 64;
    const int K = 13 * HH;

    float acc[2][8][4];
#pragma unroll
    for (int mt = 0; mt < 2; mt++)
#pragma unroll
        for (int nt = 0; nt < 8; nt++)
#pragma unroll
            for (int i = 0; i < 4; i++) acc[mt][nt][i] = 0.f;

    for (int k0 = 0; k0 < K; k0 += 16) {
#pragma unroll
        for (int i = 0; i < 2; i++) {
            int v = t + 256 * i;
            int row = v >> 2, kq = (v & 3) * 4;
            float4 av = make_float4(0.f, 0.f, 0.f, 0.f);
            int gr = m0 + row;
            if (gr < NN) {
                int kg = k0 + kq;
                if (kg < HH) {
                    av = *(const float4*)(g_x + (size_t)gr * HH + kg);
                } else {
                    int kk = kg - HH;
                    int sec = kk >> 9;
                    int j = kk & 511;
                    av = *(const float4*)(g_agg + (size_t)gr * 512 + j);
                    if (sec != 0) {
                        float s = (sec == 1) ? g_amp[gr] : g_att[gr];
                        av.x *= s; av.y *= s; av.z *= s; av.w *= s;
                    }
                }
            }
            *(uint4*)&As[row][kq] = tf32r4(av);
            int kb = v >> 5, nq = (v & 31) * 4;
            float4 bv = *(const float4*)(g_Wfold + (size_t)(k0 + kb) * HH + nq);
            *(uint4*)&Bs[kb][nq] = tf32r4(bv);
        }
        __syncthreads();
#pragma unroll
        for (int kk = 0; kk < 16; kk += 8) {
            unsigned af[2][4];
#pragma unroll
            for (int mt = 0; mt < 2; mt++) {
                int r = wm + mt * 16 + gid;
                af[mt][0] = As[r][kk + tq];
                af[mt][1] = As[r + 8][kk + tq];
                af[mt][2] = As[r][kk + tq + 4];
                af[mt][3] = As[r + 8][kk + tq + 4];
            }
#pragma unroll
            for (int nt = 0; nt < 8; nt++) {
                unsigned bf[2];
                bf[0] = Bs[kk + tq][wn + nt * 8 + gid];
                bf[1] = Bs[kk + tq + 4][wn + nt * 8 + gid];
                mma_tf32(acc[0][nt], af[0], bf);
                mma_tf32(acc[1][nt], af[1], bf);
            }
        }
        __syncthreads();
    }

#pragma unroll
    for (int nt = 0; nt < 8; nt++) {
        int col = wn + nt * 8 + tq * 2;
        float bx = g_bias2[col], by = g_bias2[col + 1];
#pragma unroll
        for (int mt = 0; mt < 2; mt++) {
            int r0 = m0 + wm + mt * 16 + gid;
            int r1 = r0 + 8;
            if (r0 < NN) {
                float2 o = make_float2(acc[mt][nt][0] + bx, acc[mt][nt][1] + by);
                *(float2*)(g_n1 + (size_t)r0 * HH + col) = o;
            }
            if (r1 < NN) {
                float2 o = make_float2(acc[mt][nt][2] + bx, acc[mt][nt][3] + by);
                *(float2*)(g_n1 + (size_t)r1 * HH + col) = o;
            }
        }
    }
}

// ---------------- exact fp32 SIMT GEMM (kept for tiny weight folds) -----------
__global__ __launch_bounds__(256) void k_gemm(
    const float* __restrict__ A, const float* __restrict__ B,
    const float* __restrict__ bias, float* __restrict__ C,
    int M, int K, float alpha, float beta, float bscale)
{
    __shared__ float As[64][16];
    __shared__ float Bs[16][128];
    const int t = threadIdx.x;
    const int m0 = blockIdx.x * 64;
    const int lane = t & 31;
    const int wrow = (t >> 5) * 8;
    const int col0 = lane * 4;
    const int ar = t >> 2;
    const int ak = (t & 3) * 4;
    const int br = t >> 4;
    const int bc = (t & 15) * 8;

    float acc[8][4];
#pragma unroll
    for (int i = 0; i < 8; i++) { acc[i][0]=0.f; acc[i][1]=0.f; acc[i][2]=0.f; acc[i][3]=0.f; }

    for (int k0 = 0; k0 < K; k0 += 16) {
        float4 av = make_float4(0.f,0.f,0.f,0.f);
        int grow = m0 + ar;
        if (grow < M) av = *(const float4*)(A + (size_t)grow * K + k0 + ak);
        *(float4*)&As[ar][ak] = av;
        *(float4*)&Bs[br][bc]     = *(const float4*)(B + (size_t)(k0 + br) * HH + bc);
        *(float4*)&Bs[br][bc + 4] = *(const float4*)(B + (size_t)(k0 + br) * HH + bc + 4);
        __syncthreads();
#pragma unroll
        for (int k = 0; k < 16; k++) {
            float4 b = *(const float4*)&Bs[k][col0];
#pragma unroll
            for (int i = 0; i < 8; i++) {
                float a = As[wrow + i][k];
                acc[i][0] = fmaf(a, b.x, acc[i][0]);
                acc[i][1] = fmaf(a, b.y, acc[i][1]);
                acc[i][2] = fmaf(a, b.z, acc[i][2]);
                acc[i][3] = fmaf(a, b.w, acc[i][3]);
            }
        }
        __syncthreads();
    }

    float4 bv = make_float4(0.f,0.f,0.f,0.f);
    if (bias) {
        bv = *(const float4*)(bias + col0);
        bv.x *= bscale; bv.y *= bscale; bv.z *= bscale; bv.w *= bscale;
    }
#pragma unroll
    for (int i = 0; i < 8; i++) {
        int r = m0 + wrow + i;
        if (r < M) {
            float4 o;
            o.x = acc[i][0] * alpha + bv.x;
            o.y = acc[i][1] * alpha + bv.y;
            o.z = acc[i][2] * alpha + bv.z;
            o.w = acc[i][3] * alpha + bv.w;
            if (beta != 0.f) {
                float4 c = *(const float4*)(C + (size_t)r * HH + col0);
                o.x += beta * c.x; o.y += beta * c.y; o.z += beta * c.z; o.w += beta * c.w;
            }
            *(float4*)(C + (size_t)r * HH + col0) = o;
        }
    }
}

// ---------------- small kernels ----------------------------------------------
__global__ void k_zero(float* p, int n) {
    int i = blockIdx.x * blockDim.x + threadIdx.x;
    if (i < n) p[i] = 0.f;
}

__global__ void k_degacc(const int* __restrict__ dst) {
    int i = blockIdx.x * blockDim.x + threadIdx.x;
    if (i < EE) atomicAdd(&g_deg[dst[i]], 1.0f);
}

__global__ void k_nodestats(const float* __restrict__ adl_p) {
    int n = blockIdx.x * blockDim.x + threadIdx.x;
    if (n >= NN) return;
    float adl = __ldg(adl_p);
    float d = g_deg[n];
    float degc = fmaxf(d, 1.0f);
    float lg = logf(degc + 1.0f);
    g_amp[n]  = lg / adl;
    g_att[n]  = adl / lg;
    g_dinv[n] = 1.0f / degc;
    g_has[n]  = (d > 0.f) ? 1.f : 0.f;
}

__global__ void k_vecmat(const float* __restrict__ v, const float* __restrict__ W,
                         const float* __restrict__ b0, float* __restrict__ out) {
    int j = threadIdx.x;
    float s = b0[j];
    for (int k = 0; k < HH; k++) s = fmaf(v[k], W[k * HH + j], s);
    out[j] = s;
}

__global__ void k_initagg() {
    int i = blockIdx.x * blockDim.x + threadIdx.x;
    if (i >= NN * HH) return;
    g_s1[i] = 0.f;
    g_s2[i] = 0.f;
    g_mn[i] = 0xFF800000u;
    g_mx[i] = 0x007FFFFFu;
}

__global__ __launch_bounds__(256) void k_msg(const int* __restrict__ src, const int* __restrict__ dst) {
    int e = blockIdx.x * 8 + (threadIdx.x >> 5);
    int lane = threadIdx.x & 31;
    int c = lane * 4;
    int s = __ldg(src + e);
    int d = __ldg(dst + e);
    float4 a  = *(const float4*)(g_n1 + (size_t)d * HH + c);
    float4 b  = *(const float4*)(g_n2 + (size_t)s * HH + c);
    float4 w  = *(const float4*)(g_eb1 + (size_t)e * HH + c);
    float4 bb = *(const float4*)(g_bias1 + c);
    float h[4] = { a.x + b.x + w.x + bb.x, a.y + b.y + w.y + bb.y,
                   a.z + b.z + w.z + bb.z, a.w + b.w + w.w + bb.w };
    size_t base = (size_t)d * HH + c;
#pragma unroll
    for (int j = 0; j < 4; j++) {
        float hv = h[j];
        atomicAdd(&g_s1[base + j], hv);
        atomicAdd(&g_s2[base + j], hv * hv);
        unsigned u = fenc(hv);
        atomicMin(&g_mn[base + j], u);
        atomicMax(&g_mx[base + j], u);
    }
}

__global__ void k_makeagg() {
    int i = blockIdx.x * blockDim.x + threadIdx.x;
    if (i >= NN * HH) return;
    int n = i >> 7;
    int c = i & 127;
    float s1 = g_s1[i], s2 = g_s2[i];
    float dinv = g_dinv[n];
    float has = g_has[n];
    float mean = s1 * dinv;
    float var = fmaxf(s2 * dinv - mean * mean, 0.f);
    float sd = sqrtf(var + 1e-5f);
    float mn = (has > 0.f) ? fdec(g_mn[i]) : 0.f;
    float mx = (has > 0.f) ? fdec(g_mx[i]) : 0.f;
    size_t b = (size_t)n * 512;
    g_agg[b + c]       = mean;
    g_agg[b + 128 + c] = mn;
    g_agg[b + 256 + c] = mx;
    g_agg[b + 384 + c] = sd;
}

__global__ void k_bnzero() {
    int t = threadIdx.x;
    g_bns[t] = 0.f;
    g_bnq[t] = 0.f;
}

__global__ __launch_bounds__(256) void k_bnred() {
    __shared__ float sh[256], shq[256];
    int t = threadIdx.x;
    int col = t & 127;
    int half = t >> 7;
    float s = 0.f, q = 0.f;
    for (int row = blockIdx.x * 2 + half; row < NN; row += gridDim.x * 2) {
        float v = g_n1[(size_t)row * HH + col];
        s += v; q += v * v;
    }
    sh[t] = s; shq[t] = q;
    __syncthreads();
    if (half == 0) {
        atomicAdd(&g_bns[col], s + sh[t + 128]);
        atomicAdd(&g_bnq[col], q + shq[t + 128]);
    }
}

__global__ void k_bnapply(const float* __restrict__ gamma, const float* __restrict__ beta) {
    int i = blockIdx.x * blockDim.x + threadIdx.x;
    if (i >= NN * HH) return;
    int c = i & 127;
    const float invN = 1.0f / (float)NN;
    float mu = g_bns[c] * invN;
    float var = g_bnq[c] * invN - mu * mu;
    float v = g_n1[i];
    float bn = gamma[c] * (v - mu) * rsqrtf(var + 1e-5f) + beta[c];
    g_x[i] = (g_x[i] + fmaxf(bn, 0.f)) * 0.5f;
}

__global__ void k_upd(const int* __restrict__ src, const int* __restrict__ dst,
                      const float* __restrict__ b1) {
    int idx = blockIdx.x * blockDim.x + threadIdx.x;
    int e = idx >> 5;
    int c = (idx & 31) * 4;
    int s = __ldg(src + e);
    int d = __ldg(dst + e);
    float4 a  = *(const float4*)(g_n1 + (size_t)s * HH + c);
    float4 b  = *(const float4*)(g_n2 + (size_t)d * HH + c);
    float4 w  = *(const float4*)(g_eb1 + (size_t)e * HH + c);
    float4 bb = *(const float4*)(b1 + c);
    float4 o;
    o.x = fmaxf(a.x + b.x + w.x + bb.x, 0.f);
    o.y = fmaxf(a.y + b.y + w.y + bb.y, 0.f);
    o.z = fmaxf(a.z + b.z + w.z + bb.z, 0.f);
    o.w = fmaxf(a.w + b.w + w.w + bb.w, 0.f);
    *(float4*)(g_eb2 + (size_t)e * HH + c) = o;
}

__global__ void k_copy(float* __restrict__ out) {
    int i = blockIdx.x * blockDim.x + threadIdx.x;
    if (i < NN * HH) out[i] = g_x[i];
}

// ---------------- host orchestration -----------------------------------------
extern "C" void kernel_launch(void* const* d_in, const int* in_sizes, int n_in,
                              void* d_out, int out_size) {
    const float* x_in   = (const float*)d_in[0];
    const int*   ei     = (const int*)d_in[1];
    const float* eattr  = (const float*)d_in[2];
    const float* pattr  = (const float*)d_in[4];
    const float* nattr  = (const float*)d_in[6];
    const float* adl    = (const float*)d_in[7];
    const float* node_w = (const float*)d_in[8];
    const float* node_b = (const float*)d_in[9];
    const float* edge_w = (const float*)d_in[10];
    const float* edge_b = (const float*)d_in[11];
    const float* eenc_w = (const float*)d_in[12];
    const float* eenc_b = (const float*)d_in[13];
    const float* pre_w  = (const float*)d_in[14];
    const float* pre_b  = (const float*)d_in[15];
    const float* post_w = (const float*)d_in[16];
    const float* post_b = (const float*)d_in[17];
    const float* lin_w  = (const float*)d_in[18];
    const float* lin_b  = (const float*)d_in[19];
    const float* ew1    = (const float*)d_in[20];
    const float* eb1v   = (const float*)d_in[21];
    const float* ew2    = (const float*)d_in[22];
    const float* eb2v   = (const float*)d_in[23];
    const float* bng    = (const float*)d_in[24];
    const float* bnb    = (const float*)d_in[25];
    float* out = (float*)d_out;

    float *p_x, *p_ea, *p_n1, *p_n2, *p_eb1, *p_eb2, *p_W3, *p_Wfold, *p_b1, *p_b2, *p_deg;
    cudaGetSymbolAddress((void**)&p_x, g_x);
    cudaGetSymbolAddress((void**)&p_ea, g_ea);
    cudaGetSymbolAddress((void**)&p_n1, g_n1);
    cudaGetSymbolAddress((void**)&p_n2, g_n2);
    cudaGetSymbolAddress((void**)&p_eb1, g_eb1);
    cudaGetSymbolAddress((void**)&p_eb2, g_eb2);
    cudaGetSymbolAddress((void**)&p_W3, g_W3);
    cudaGetSymbolAddress((void**)&p_Wfold, g_Wfold);
    cudaGetSymbolAddress((void**)&p_b1, g_bias1);
    cudaGetSymbolAddress((void**)&p_b2, g_bias2);
    cudaGetSymbolAddress((void**)&p_deg, g_deg);

    const int* src = ei;
    const int* dst = ei + EE;

    // tensor-core GEMM for all large matmuls
    auto gemm = [](const float* A, const float* B, const float* bias, float* C,
                   int M, int K, float alpha, float beta, float bscale) {
        k_gemm_tc<<<(M + 127) / 128, 256>>>(A, B, bias, C, M, K, alpha, beta, bscale);
    };
    // exact fp32 for tiny weight folds
    auto gemm_exact = [](const float* A, const float* B, const float* bias, float* C,
                         int M, int K, float alpha, float beta, float bscale) {
        k_gemm<<<(M + 63) / 64, 256>>>(A, B, bias, C, M, K, alpha, beta, bscale);
    };

    // degree stats (fixed across layers)
    k_zero<<<(NN + 255) / 256, 256>>>(p_deg, NN);
    k_degacc<<<(EE + 255) / 256, 256>>>(dst);
    k_nodestats<<<(NN + 255) / 256, 256>>>(adl);

    // embeddings
    gemm(x_in, node_w, node_b, p_x, NN, 64, 1.f, 0.f, 1.f);
    gemm(eattr, edge_w, edge_b, p_ea, EE, 32, 1.f, 0.f, 1.f);
    gemm(pattr, edge_w, edge_b, out + (size_t)NN * HH, EPP, 32, 1.f, 0.f, 1.f);
    gemm(nattr, edge_w, edge_b, out + (size_t)NN * HH + (size_t)EPP * HH, EPP, 32, 1.f, 0.f, 1.f);

    for (int l = 0; l < 2; l++) {
        const float* preW = pre_w + (size_t)l * 384 * HH;
        const float* postW = post_w + (size_t)l * 1664 * HH;
        const float* linW = lin_w + (size_t)l * HH * HH;
        const float* e1W = ew1 + (size_t)l * 384 * HH;
        const float* e2W = ew2 + (size_t)l * HH * HH;

        // weight/bias folds (exact fp32)
        gemm_exact(eenc_w + (size_t)l * HH * HH, preW + 256 * HH, nullptr, p_W3, HH, HH, 1.f, 0.f, 0.f);
        k_vecmat<<<1, 128>>>(eenc_b + l * HH, preW + 256 * HH, pre_b + l * HH, p_b1);
        gemm_exact(postW, linW, nullptr, p_Wfold, 13 * HH, HH, 1.f, 0.f, 0.f);
        k_vecmat<<<1, 128>>>(post_b + l * HH, linW, lin_b + l * HH, p_b2);

        // message projections (tensor cores)
        gemm(p_x, preW, nullptr, p_n1, NN, HH, 1.f, 0.f, 0.f);            // x@P0 (dst side)
        gemm(p_x, preW + 128 * HH, nullptr, p_n2, NN, HH, 1.f, 0.f, 0.f); // x@P1 (src side)
        gemm(p_ea, p_W3, nullptr, p_eb1, EE, HH, 1.f, 0.f, 0.f);          // ea@(Ee@P2)

        // aggregate
        k_initagg<<<(NN * HH + 255) / 256, 256>>>();
        k_msg<<<EE / 8, 256>>>(src, dst);
        k_makeagg<<<(NN * HH + 255) / 256, 256>>>();

        // node update: fused post+lin (tensor cores), then BN + residual
        k_post_tc<<<(NN + 127) / 128, 256>>>();
        k_bnzero<<<1, 128>>>();
        k_bnred<<<256, 256>>>();
        k_bnapply<<<(NN * HH + 255) / 256, 256>>>(bng + l * HH, bnb + l * HH);

        // edge update
        gemm(p_x, e1W, nullptr, p_n1, NN, HH, 1.f, 0.f, 0.f);            // x@U0 (src side)
        gemm(p_x, e1W + 128 * HH, nullptr, p_n2, NN, HH, 1.f, 0.f, 0.f); // x@U1 (dst side)
        gemm(p_ea, e1W + 256 * HH, nullptr, p_eb1, EE, HH, 1.f, 0.f, 0.f);
        k_upd<<<(EE * 32 + 255) / 256, 256>>>(src, dst, eb1v + l * HH);
        gemm(p_eb2, e2W, eb2v + l * HH, p_ea, EE, HH, 0.5f, 1.f, 0.5f);
    }

    k_copy<<<(NN * HH + 255) / 256, 256>>>(out);
}

// round 8
// speedup vs baseline: 2.1202x; 1.3245x over previous
#include <cuda_runtime.h>
#include <math.h>

#define NN 50000
#define EE 400000
#define EPP 40000
#define HH 128
#define NB ((NN + 1023) / 1024)

// ---------------- scratch (device globals; no runtime allocation) ------------
__device__ __align__(16) float    g_x[(size_t)NN*HH];
__device__ __align__(16) float    g_n1[(size_t)NN*HH];
__device__ __align__(16) float    g_n2[(size_t)NN*HH];
__device__ __align__(16) float    g_agg[(size_t)NN*4*HH];
__device__ __align__(16) float    g_ea[(size_t)EE*HH];
__device__ __align__(16) float    g_eb1[(size_t)EE*HH];
__device__ float g_amp[NN];
__device__ float g_att[NN];
__device__ __align__(16) float g_W3[HH*HH];
__device__ __align__(16) float g_Wfold[13*HH*HH];
__device__ __align__(16) float g_bias1[HH];
__device__ __align__(16) float g_bias2[HH];
__device__ float g_bns[HH];
__device__ float g_bnq[HH];
// CSR
__device__ int g_degi[NN];
__device__ int g_rowptr[NN + 1];
__device__ int g_cursor[NN];
__device__ int g_blocksum[64];
__device__ int g_eperm[EE];
__device__ int g_srcs[EE];

// ---------------- helpers ----------------------------------------------------
__device__ __forceinline__ unsigned tf32r(float f) {
    unsigned u;
    asm("cvt.rna.tf32.f32 %0, %1;" : "=r"(u) : "f"(f));
    return u;
}
__device__ __forceinline__ uint4 tf32r4(float4 v) {
    uint4 o;
    o.x = tf32r(v.x); o.y = tf32r(v.y); o.z = tf32r(v.z); o.w = tf32r(v.w);
    return o;
}
__device__ __forceinline__ void mma_tf32(float* d, const unsigned* a, const unsigned* b) {
    asm volatile(
        "mma.sync.aligned.m16n8k8.row.col.f32.tf32.tf32.f32 "
        "{%0,%1,%2,%3}, {%4,%5,%6,%7}, {%8,%9}, {%0,%1,%2,%3};"
        : "+f"(d[0]), "+f"(d[1]), "+f"(d[2]), "+f"(d[3])
        : "r"(a[0]), "r"(a[1]), "r"(a[2]), "r"(a[3]), "r"(b[0]), "r"(b[1]));
}

// ---------------- tensor-core tf32 GEMM (optional A row gather) ---------------
// C[M,128] = alpha*A[idx(M),K]@B[K,128] + bscale*bias + beta*C
__global__ __launch_bounds__(256, 2) void k_gemm_tc(
    const float* __restrict__ A, const float* __restrict__ B,
    const float* __restrict__ bias, float* __restrict__ C,
    const int* __restrict__ Aidx,
    int M, int K, float alpha, float beta, float bscale)
{
    __shared__ unsigned As[128][20];
    __shared__ unsigned Bs[16][136];
    const int t = threadIdx.x;
    const int m0 = blockIdx.x * 128;
    const int warp = t >> 5, lane = t & 31;
    const int gid = lane >> 2, tq = lane & 3;
    const int wm = (warp >> 1) * 32, wn = (warp & 1) * 64;

    float acc[2][8][4];
#pragma unroll
    for (int mt = 0; mt < 2; mt++)
#pragma unroll
        for (int nt = 0; nt < 8; nt++)
#pragma unroll
            for (int i = 0; i < 4; i++) acc[mt][nt][i] = 0.f;

    for (int k0 = 0; k0 < K; k0 += 16) {
#pragma unroll
        for (int i = 0; i < 2; i++) {
            int v = t + 256 * i;
            int row = v >> 2, kq = (v & 3) * 4;
            float4 av = make_float4(0.f, 0.f, 0.f, 0.f);
            int gr = m0 + row;
            if (gr < M) {
                int ar = Aidx ? __ldg(Aidx + gr) : gr;
                av = *(const float4*)(A + (size_t)ar * K + k0 + kq);
            }
            *(uint4*)&As[row][kq] = tf32r4(av);
            int kb = v >> 5, nq = (v & 31) * 4;
            float4 bv = *(const float4*)(B + (size_t)(k0 + kb) * HH + nq);
            *(uint4*)&Bs[kb][nq] = tf32r4(bv);
        }
        __syncthreads();
#pragma unroll
        for (int kk = 0; kk < 16; kk += 8) {
            unsigned af[2][4];
#pragma unroll
            for (int mt = 0; mt < 2; mt++) {
                int r = wm + mt * 16 + gid;
                af[mt][0] = As[r][kk + tq];
                af[mt][1] = As[r + 8][kk + tq];
                af[mt][2] = As[r][kk + tq + 4];
                af[mt][3] = As[r + 8][kk + tq + 4];
            }
#pragma unroll
            for (int nt = 0; nt < 8; nt++) {
                unsigned bf[2];
                bf[0] = Bs[kk + tq][wn + nt * 8 + gid];
                bf[1] = Bs[kk + tq + 4][wn + nt * 8 + gid];
                mma_tf32(acc[0][nt], af[0], bf);
                mma_tf32(acc[1][nt], af[1], bf);
            }
        }
        __syncthreads();
    }

#pragma unroll
    for (int nt = 0; nt < 8; nt++) {
        int col = wn + nt * 8 + tq * 2;
        float bx = 0.f, by = 0.f;
        if (bias) { bx = bias[col] * bscale; by = bias[col + 1] * bscale; }
#pragma unroll
        for (int mt = 0; mt < 2; mt++) {
            int r0 = m0 + wm + mt * 16 + gid;
            int r1 = r0 + 8;
            if (r0 < M) {
                float2 o;
                o.x = acc[mt][nt][0] * alpha + bx;
                o.y = acc[mt][nt][1] * alpha + by;
                if (beta != 0.f) {
                    float2 c = *(const float2*)(C + (size_t)r0 * HH + col);
                    o.x += beta * c.x; o.y += beta * c.y;
                }
                *(float2*)(C + (size_t)r0 * HH + col) = o;
            }
            if (r1 < M) {
                float2 o;
                o.x = acc[mt][nt][2] * alpha + bx;
                o.y = acc[mt][nt][3] * alpha + by;
                if (beta != 0.f) {
                    float2 c = *(const float2*)(C + (size_t)r1 * HH + col);
                    o.x += beta * c.x; o.y += beta * c.y;
                }
                *(float2*)(C + (size_t)r1 * HH + col) = o;
            }
        }
    }
}

// ---------------- fused edge-update GEMM:
// ea[e] += 0.5 * relu(n1[src[e]] + n2[dst[e]] + eb1[e] + b1) @ W2 + 0.5*b2
__global__ __launch_bounds__(256, 2) void k_gemm_upd_tc(
    const int* __restrict__ srcp, const int* __restrict__ dstp,
    const float* __restrict__ b1, const float* __restrict__ W2,
    const float* __restrict__ b2)
{
    __shared__ unsigned As[128][20];
    __shared__ unsigned Bs[16][136];
    const int t = threadIdx.x;
    const int m0 = blockIdx.x * 128;
    const int warp = t >> 5, lane = t & 31;
    const int gid = lane >> 2, tq = lane & 3;
    const int wm = (warp >> 1) * 32, wn = (warp & 1) * 64;

    float acc[2][8][4];
#pragma unroll
    for (int mt = 0; mt < 2; mt++)
#pragma unroll
        for (int nt = 0; nt < 8; nt++)
#pragma unroll
            for (int i = 0; i < 4; i++) acc[mt][nt][i] = 0.f;

    for (int k0 = 0; k0 < HH; k0 += 16) {
#pragma unroll
        for (int i = 0; i < 2; i++) {
            int v = t + 256 * i;
            int row = v >> 2, kq = (v & 3) * 4;
            int e = m0 + row;
            int kg = k0 + kq;
            int s = __ldg(srcp + e);
            int d = __ldg(dstp + e);
            float4 a1 = *(const float4*)(g_n1 + (size_t)s * HH + kg);
            float4 a2 = *(const float4*)(g_n2 + (size_t)d * HH + kg);
            float4 w  = *(const float4*)(g_eb1 + (size_t)e * HH + kg);
            float4 bb = *(const float4*)(b1 + kg);
            float4 av;
            av.x = fmaxf(a1.x + a2.x + w.x + bb.x, 0.f);
            av.y = fmaxf(a1.y + a2.y + w.y + bb.y, 0.f);
            av.z = fmaxf(a1.z + a2.z + w.z + bb.z, 0.f);
            av.w = fmaxf(a1.w + a2.w + w.w + bb.w, 0.f);
            *(uint4*)&As[row][kq] = tf32r4(av);
            int kb = v >> 5, nq = (v & 31) * 4;
            float4 bv = *(const float4*)(W2 + (size_t)(k0 + kb) * HH + nq);
            *(uint4*)&Bs[kb][nq] = tf32r4(bv);
        }
        __syncthreads();
#pragma unroll
        for (int kk = 0; kk < 16; kk += 8) {
            unsigned af[2][4];
#pragma unroll
            for (int mt = 0; mt < 2; mt++) {
                int r = wm + mt * 16 + gid;
                af[mt][0] = As[r][kk + tq];
                af[mt][1] = As[r + 8][kk + tq];
                af[mt][2] = As[r][kk + tq + 4];
                af[mt][3] = As[r + 8][kk + tq + 4];
            }
#pragma unroll
            for (int nt = 0; nt < 8; nt++) {
                unsigned bf[2];
                bf[0] = Bs[kk + tq][wn + nt * 8 + gid];
                bf[1] = Bs[kk + tq + 4][wn + nt * 8 + gid];
                mma_tf32(acc[0][nt], af[0], bf);
                mma_tf32(acc[1][nt], af[1], bf);
            }
        }
        __syncthreads();
    }

#pragma unroll
    for (int nt = 0; nt < 8; nt++) {
        int col = wn + nt * 8 + tq * 2;
        float bx = b2[col] * 0.5f, by = b2[col + 1] * 0.5f;
#pragma unroll
        for (int mt = 0; mt < 2; mt++) {
            int r0 = m0 + wm + mt * 16 + gid;
            int r1 = r0 + 8;
            {
                float2 c = *(const float2*)(g_ea + (size_t)r0 * HH + col);
                float2 o = make_float2(acc[mt][nt][0] * 0.5f + bx + c.x,
                                       acc[mt][nt][1] * 0.5f + by + c.y);
                *(float2*)(g_ea + (size_t)r0 * HH + col) = o;
            }
            {
                float2 c = *(const float2*)(g_ea + (size_t)r1 * HH + col);
                float2 o = make_float2(acc[mt][nt][2] * 0.5f + bx + c.x,
                                       acc[mt][nt][3] * 0.5f + by + c.y);
                *(float2*)(g_ea + (size_t)r1 * HH + col) = o;
            }
        }
    }
}

// ---------------- fused post+lin on tensor cores ------------------------------
__global__ __launch_bounds__(256, 2) void k_post_tc()
{
    __shared__ unsigned As[128][20];
    __shared__ unsigned Bs[16][136];
    const int t = threadIdx.x;
    const int m0 = blockIdx.x * 128;
    const int warp = t >> 5, lane = t & 31;
    const int gid = lane >> 2, tq = lane & 3;
    const int wm = (warp >> 1) * 32, wn = (warp & 1) * 64;
    const int K = 13 * HH;

    float acc[2][8][4];
#pragma unroll
    for (int mt = 0; mt < 2; mt++)
#pragma unroll
        for (int nt = 0; nt < 8; nt++)
#pragma unroll
            for (int i = 0; i < 4; i++) acc[mt][nt][i] = 0.f;

    for (int k0 = 0; k0 < K; k0 += 16) {
#pragma unroll
        for (int i = 0; i < 2; i++) {
            int v = t + 256 * i;
            int row = v >> 2, kq = (v & 3) * 4;
            float4 av = make_float4(0.f, 0.f, 0.f, 0.f);
            int gr = m0 + row;
            if (gr < NN) {
                int kg = k0 + kq;
                if (kg < HH) {
                    av = *(const float4*)(g_x + (size_t)gr * HH + kg);
                } else {
                    int kk = kg - HH;
                    int sec = kk >> 9;
                    int j = kk & 511;
                    av = *(const float4*)(g_agg + (size_t)gr * 512 + j);
                    if (sec != 0) {
                        float s = (sec == 1) ? g_amp[gr] : g_att[gr];
                        av.x *= s; av.y *= s; av.z *= s; av.w *= s;
                    }
                }
            }
            *(uint4*)&As[row][kq] = tf32r4(av);
            int kb = v >> 5, nq = (v & 31) * 4;
            float4 bv = *(const float4*)(g_Wfold + (size_t)(k0 + kb) * HH + nq);
            *(uint4*)&Bs[kb][nq] = tf32r4(bv);
        }
        __syncthreads();
#pragma unroll
        for (int kk = 0; kk < 16; kk += 8) {
            unsigned af[2][4];
#pragma unroll
            for (int mt = 0; mt < 2; mt++) {
                int r = wm + mt * 16 + gid;
                af[mt][0] = As[r][kk + tq];
                af[mt][1] = As[r + 8][kk + tq];
                af[mt][2] = As[r][kk + tq + 4];
                af[mt][3] = As[r + 8][kk + tq + 4];
            }
#pragma unroll
            for (int nt = 0; nt < 8; nt++) {
                unsigned bf[2];
                bf[0] = Bs[kk + tq][wn + nt * 8 + gid];
                bf[1] = Bs[kk + tq + 4][wn + nt * 8 + gid];
                mma_tf32(acc[0][nt], af[0], bf);
                mma_tf32(acc[1][nt], af[1], bf);
            }
        }
        __syncthreads();
    }

#pragma unroll
    for (int nt = 0; nt < 8; nt++) {
        int col = wn + nt * 8 + tq * 2;
        float bx = g_bias2[col], by = g_bias2[col + 1];
#pragma unroll
        for (int mt = 0; mt < 2; mt++) {
            int r0 = m0 + wm + mt * 16 + gid;
            int r1 = r0 + 8;
            if (r0 < NN) {
                float2 o = make_float2(acc[mt][nt][0] + bx, acc[mt][nt][1] + by);
                *(float2*)(g_n1 + (size_t)r0 * HH + col) = o;
            }
            if (r1 < NN) {
                float2 o = make_float2(acc[mt][nt][2] + bx, acc[mt][nt][3] + by);
                *(float2*)(g_n1 + (size_t)r1 * HH + col) = o;
            }
        }
    }
}

// ---------------- exact fp32 SIMT GEMM (tiny weight folds) --------------------
__global__ __launch_bounds__(256) void k_gemm(
    const float* __restrict__ A, const float* __restrict__ B,
    float* __restrict__ C, int M, int K)
{
    __shared__ float As[64][16];
    __shared__ float Bs[16][128];
    const int t = threadIdx.x;
    const int m0 = blockIdx.x * 64;
    const int lane = t & 31;
    const int wrow = (t >> 5) * 8;
    const int col0 = lane * 4;
    const int ar = t >> 2;
    const int ak = (t & 3) * 4;
    const int br = t >> 4;
    const int bc = (t & 15) * 8;

    float acc[8][4];
#pragma unroll
    for (int i = 0; i < 8; i++) { acc[i][0]=0.f; acc[i][1]=0.f; acc[i][2]=0.f; acc[i][3]=0.f; }

    for (int k0 = 0; k0 < K; k0 += 16) {
        float4 av = make_float4(0.f,0.f,0.f,0.f);
        int grow = m0 + ar;
        if (grow < M) av = *(const float4*)(A + (size_t)grow * K + k0 + ak);
        *(float4*)&As[ar][ak] = av;
        *(float4*)&Bs[br][bc]     = *(const float4*)(B + (size_t)(k0 + br) * HH + bc);
        *(float4*)&Bs[br][bc + 4] = *(const float4*)(B + (size_t)(k0 + br) * HH + bc + 4);
        __syncthreads();
#pragma unroll
        for (int k = 0; k < 16; k++) {
            float4 b = *(const float4*)&Bs[k][col0];
#pragma unroll
            for (int i = 0; i < 8; i++) {
                float a = As[wrow + i][k];
                acc[i][0] = fmaf(a, b.x, acc[i][0]);
                acc[i][1] = fmaf(a, b.y, acc[i][1]);
                acc[i][2] = fmaf(a, b.z, acc[i][2]);
                acc[i][3] = fmaf(a, b.w, acc[i][3]);
            }
        }
        __syncthreads();
    }
#pragma unroll
    for (int i = 0; i < 8; i++) {
        int r = m0 + wrow + i;
        if (r < M) {
            float4 o = make_float4(acc[i][0], acc[i][1], acc[i][2], acc[i][3]);
            *(float4*)(C + (size_t)r * HH + col0) = o;
        }
    }
}

// ---------------- CSR build ---------------------------------------------------
__global__ void k_zeroi(int* p, int n) {
    int i = blockIdx.x * blockDim.x + threadIdx.x;
    if (i < n) p[i] = 0;
}
__global__ void k_degacc(const int* __restrict__ dst) {
    int i = blockIdx.x * blockDim.x + threadIdx.x;
    if (i < EE) atomicAdd(&g_degi[dst[i]], 1);
}
__global__ __launch_bounds__(1024) void k_scan1() {
    __shared__ int sh[1024];
    int i = blockIdx.x * 1024 + threadIdx.x;
    int v = (i < NN) ? g_degi[i] : 0;
    sh[threadIdx.x] = v;
    __syncthreads();
    for (int off = 1; off < 1024; off <<= 1) {
        int tv = (threadIdx.x >= off) ? sh[threadIdx.x - off] : 0;
        __syncthreads();
        sh[threadIdx.x] += tv;
        __syncthreads();
    }
    if (i < NN) g_rowptr[i + 1] = sh[threadIdx.x];
    if (threadIdx.x == 1023) g_blocksum[blockIdx.x] = sh[1023];
}
__global__ void k_scan2() {
    if (threadIdx.x == 0) {
        int s = 0;
        for (int b = 0; b < NB; b++) { int v = g_blocksum[b]; g_blocksum[b] = s; s += v; }
    }
}
__global__ __launch_bounds__(1024) void k_scan3() {
    int i = blockIdx.x * 1024 + threadIdx.x;
    if (i < NN) g_rowptr[i + 1] += g_blocksum[i >> 10];
    if (i == 0) g_rowptr[0] = 0;
}
__global__ void k_cursor() {
    int i = blockIdx.x * blockDim.x + threadIdx.x;
    if (i < NN) g_cursor[i] = g_rowptr[i];
}
__global__ void k_scatter(const int* __restrict__ src, const int* __restrict__ dst) {
    int e = blockIdx.x * blockDim.x + threadIdx.x;
    if (e >= EE) return;
    int d = dst[e];
    int p = atomicAdd(&g_cursor[d], 1);
    g_eperm[p] = e;
    g_srcs[p] = src[e];
}

// ---------------- small kernels ----------------------------------------------
__global__ void k_nodestats(const float* __restrict__ adl_p) {
    int n = blockIdx.x * blockDim.x + threadIdx.x;
    if (n >= NN) return;
    float adl = __ldg(adl_p);
    float d = (float)(g_rowptr[n + 1] - g_rowptr[n]);
    float degc = fmaxf(d, 1.0f);
    float lg = logf(degc + 1.0f);
    g_amp[n] = lg / adl;
    g_att[n] = adl / lg;
}

__global__ void k_vecmat(const float* __restrict__ v, const float* __restrict__ W,
                         const float* __restrict__ b0, float* __restrict__ out) {
    int j = threadIdx.x;
    float s = b0[j];
    for (int k = 0; k < HH; k++) s = fmaf(v[k], W[k * HH + j], s);
    out[j] = s;
}

// CSR aggregation: one warp per node, registers only, no atomics.
__global__ __launch_bounds__(256) void k_msg_csr() {
    int n = blockIdx.x * 8 + (threadIdx.x >> 5);
    if (n >= NN) return;
    int lane = threadIdx.x & 31;
    int c = lane * 4;
    float4 bb = *(const float4*)(g_bias1 + c);
    float4 xd = *(const float4*)(g_n1 + (size_t)n * HH + c);
    float cx = xd.x + bb.x, cy = xd.y + bb.y, cz = xd.z + bb.z, cw = xd.w + bb.w;
    int beg = g_rowptr[n], end = g_rowptr[n + 1];
    float s1x = 0.f, s1y = 0.f, s1z = 0.f, s1w = 0.f;
    float s2x = 0.f, s2y = 0.f, s2z = 0.f, s2w = 0.f;
    float mnx = INFINITY, mny = INFINITY, mnz = INFINITY, mnw = INFINITY;
    float mxx = -INFINITY, mxy = -INFINITY, mxz = -INFINITY, mxw = -INFINITY;
    for (int i = beg; i < end; i++) {
        int s = __ldg(g_srcs + i);
        float4 b = *(const float4*)(g_n2 + (size_t)s * HH + c);
        float4 w = *(const float4*)(g_eb1 + (size_t)i * HH + c);
        float hx = cx + b.x + w.x;
        float hy = cy + b.y + w.y;
        float hz = cz + b.z + w.z;
        float hw = cw + b.w + w.w;
        s1x += hx; s1y += hy; s1z += hz; s1w += hw;
        s2x = fmaf(hx, hx, s2x); s2y = fmaf(hy, hy, s2y);
        s2z = fmaf(hz, hz, s2z); s2w = fmaf(hw, hw, s2w);
        mnx = fminf(mnx, hx); mny = fminf(mny, hy); mnz = fminf(mnz, hz); mnw = fminf(mnw, hw);
        mxx = fmaxf(mxx, hx); mxy = fmaxf(mxy, hy); mxz = fmaxf(mxz, hz); mxw = fmaxf(mxw, hw);
    }
    int deg = end - beg;
    float dinv = (deg > 0) ? (1.0f / (float)deg) : 1.0f;
    if (deg == 0) {
        s1x = s1y = s1z = s1w = 0.f;
        s2x = s2y = s2z = s2w = 0.f;
        mnx = mny = mnz = mnw = 0.f;
        mxx = mxy = mxz = mxw = 0.f;
    }
    float mex = s1x * dinv, mey = s1y * dinv, mez = s1z * dinv, mew = s1w * dinv;
    float sdx = sqrtf(fmaxf(s2x * dinv - mex * mex, 0.f) + 1e-5f);
    float sdy = sqrtf(fmaxf(s2y * dinv - mey * mey, 0.f) + 1e-5f);
    float sdz = sqrtf(fmaxf(s2z * dinv - mez * mez, 0.f) + 1e-5f);
    float sdw = sqrtf(fmaxf(s2w * dinv - mew * mew, 0.f) + 1e-5f);
    size_t bse = (size_t)n * 512;
    *(float4*)(g_agg + bse + c)       = make_float4(mex, mey, mez, mew);
    *(float4*)(g_agg + bse + 128 + c) = make_float4(mnx, mny, mnz, mnw);
    *(float4*)(g_agg + bse + 256 + c) = make_float4(mxx, mxy, mxz, mxw);
    *(float4*)(g_agg + bse + 384 + c) = make_float4(sdx, sdy, sdz, sdw);
}

__global__ void k_bnzero() {
    int t = threadIdx.x;
    g_bns[t] = 0.f;
    g_bnq[t] = 0.f;
}

__global__ __launch_bounds__(256) void k_bnred() {
    __shared__ float sh[256], shq[256];
    int t = threadIdx.x;
    int col = t & 127;
    int half = t >> 7;
    float s = 0.f, q = 0.f;
    for (int row = blockIdx.x * 2 + half; row < NN; row += gridDim.x * 2) {
        float v = g_n1[(size_t)row * HH + col];
        s += v; q += v * v;
    }
    sh[t] = s; shq[t] = q;
    __syncthreads();
    if (half == 0) {
        atomicAdd(&g_bns[col], s + sh[t + 128]);
        atomicAdd(&g_bnq[col], q + shq[t + 128]);
    }
}

__global__ void k_bnapply(const float* __restrict__ gamma, const float* __restrict__ beta) {
    int i = blockIdx.x * blockDim.x + threadIdx.x;
    if (i >= NN * HH) return;
    int c = i & 127;
    const float invN = 1.0f / (float)NN;
    float mu = g_bns[c] * invN;
    float var = g_bnq[c] * invN - mu * mu;
    float v = g_n1[i];
    float bn = gamma[c] * (v - mu) * rsqrtf(var + 1e-5f) + beta[c];
    g_x[i] = (g_x[i] + fmaxf(bn, 0.f)) * 0.5f;
}

__global__ void k_copy(float* __restrict__ out) {
    int i = blockIdx.x * blockDim.x + threadIdx.x;
    if (i < NN * HH) out[i] = g_x[i];
}

// ---------------- host orchestration -----------------------------------------
extern "C" void kernel_launch(void* const* d_in, const int* in_sizes, int n_in,
                              void* d_out, int out_size) {
    const float* x_in   = (const float*)d_in[0];
    const int*   ei     = (const int*)d_in[1];
    const float* eattr  = (const float*)d_in[2];
    const float* pattr  = (const float*)d_in[4];
    const float* nattr  = (const float*)d_in[6];
    const float* adl    = (const float*)d_in[7];
    const float* node_w = (const float*)d_in[8];
    const float* node_b = (const float*)d_in[9];
    const float* edge_w = (const float*)d_in[10];
    const float* edge_b = (const float*)d_in[11];
    const float* eenc_w = (const float*)d_in[12];
    const float* eenc_b = (const float*)d_in[13];
    const float* pre_w  = (const float*)d_in[14];
    const float* pre_b  = (const float*)d_in[15];
    const float* post_w = (const float*)d_in[16];
    const float* post_b = (const float*)d_in[17];
    const float* lin_w  = (const float*)d_in[18];
    const float* lin_b  = (const float*)d_in[19];
    const float* ew1    = (const float*)d_in[20];
    const float* eb1v   = (const float*)d_in[21];
    const float* ew2    = (const float*)d_in[22];
    const float* eb2v   = (const float*)d_in[23];
    const float* bng    = (const float*)d_in[24];
    const float* bnb    = (const float*)d_in[25];
    float* out = (float*)d_out;

    float *p_x, *p_ea, *p_n1, *p_n2, *p_eb1, *p_W3, *p_Wfold, *p_b1, *p_b2;
    int *p_degi, *p_eperm;
    cudaGetSymbolAddress((void**)&p_x, g_x);
    cudaGetSymbolAddress((void**)&p_ea, g_ea);
    cudaGetSymbolAddress((void**)&p_n1, g_n1);
    cudaGetSymbolAddress((void**)&p_n2, g_n2);
    cudaGetSymbolAddress((void**)&p_eb1, g_eb1);
    cudaGetSymbolAddress((void**)&p_W3, g_W3);
    cudaGetSymbolAddress((void**)&p_Wfold, g_Wfold);
    cudaGetSymbolAddress((void**)&p_b1, g_bias1);
    cudaGetSymbolAddress((void**)&p_b2, g_bias2);
    cudaGetSymbolAddress((void**)&p_degi, g_degi);
    cudaGetSymbolAddress((void**)&p_eperm, g_eperm);

    const int* src = ei;
    const int* dst = ei + EE;

    auto gemm = [](const float* A, const float* B, const float* bias, float* C,
                   const int* Aidx, int M, int K, float alpha, float beta, float bscale) {
        k_gemm_tc<<<(M + 127) / 128, 256>>>(A, B, bias, C, Aidx, M, K, alpha, beta, bscale);
    };

    // ---- CSR build (once) ----
    k_zeroi<<<(NN + 255) / 256, 256>>>(p_degi, NN);
    k_degacc<<<(EE + 255) / 256, 256>>>(dst);
    k_scan1<<<NB, 1024>>>();
    k_scan2<<<1, 32>>>();
    k_scan3<<<NB, 1024>>>();
    k_cursor<<<(NN + 255) / 256, 256>>>();
    k_scatter<<<(EE + 255) / 256, 256>>>(src, dst);
    k_nodestats<<<(NN + 255) / 256, 256>>>(adl);

    // ---- embeddings ----
    gemm(x_in, node_w, node_b, p_x, nullptr, NN, 64, 1.f, 0.f, 1.f);
    gemm(eattr, edge_w, edge_b, p_ea, nullptr, EE, 32, 1.f, 0.f, 1.f);
    gemm(pattr, edge_w, edge_b, out + (size_t)NN * HH, nullptr, EPP, 32, 1.f, 0.f, 1.f);
    gemm(nattr, edge_w, edge_b, out + (size_t)NN * HH + (size_t)EPP * HH, nullptr, EPP, 32, 1.f, 0.f, 1.f);

    for (int l = 0; l < 2; l++) {
        const float* preW = pre_w + (size_t)l * 384 * HH;
        const float* postW = post_w + (size_t)l * 1664 * HH;
        const float* linW = lin_w + (size_t)l * HH * HH;
        const float* e1W = ew1 + (size_t)l * 384 * HH;
        const float* e2W = ew2 + (size_t)l * HH * HH;

        // weight/bias folds (exact fp32) — NOTE: grid must cover all M rows (64/block)
        k_gemm<<<(HH + 63) / 64, 256>>>(eenc_w + (size_t)l * HH * HH, preW + 256 * HH, p_W3, HH, HH);
        k_vecmat<<<1, 128>>>(eenc_b + l * HH, preW + 256 * HH, pre_b + l * HH, p_b1);
        k_gemm<<<(13 * HH + 63) / 64, 256>>>(postW, linW, p_Wfold, 13 * HH, HH);
        k_vecmat<<<1, 128>>>(post_b + l * HH, linW, lin_b + l * HH, p_b2);

        // message projections
        gemm(p_x, preW, nullptr, p_n1, nullptr, NN, HH, 1.f, 0.f, 0.f);            // x@P0 (dst)
        gemm(p_x, preW + 128 * HH, nullptr, p_n2, nullptr, NN, HH, 1.f, 0.f, 0.f); // x@P1 (src)
        gemm(p_ea, p_W3, nullptr, p_eb1, p_eperm, EE, HH, 1.f, 0.f, 0.f);          // dst-sorted eb1

        // aggregate (no atomics)
        k_msg_csr<<<(NN + 7) / 8, 256>>>();

        // node update: fused post+lin, then BN + residual
        k_post_tc<<<(NN + 127) / 128, 256>>>();
        k_bnzero<<<1, 128>>>();
        k_bnred<<<256, 256>>>();
        k_bnapply<<<(NN * HH + 255) / 256, 256>>>(bng + l * HH, bnb + l * HH);

        // edge update: projections + fused relu-GEMM accumulate into ea
        gemm(p_x, e1W, nullptr, p_n1, nullptr, NN, HH, 1.f, 0.f, 0.f);            // x@U0 (src)
        gemm(p_x, e1W + 128 * HH, nullptr, p_n2, nullptr, NN, HH, 1.f, 0.f, 0.f); // x@U1 (dst)
        gemm(p_ea, e1W + 256 * HH, nullptr, p_eb1, nullptr, EE, HH, 1.f, 0.f, 0.f);
        k_gemm_upd_tc<<<EE / 128, 256>>>(src, dst, eb1v + l * HH, e2W, eb2v + l * HH);
    }

    k_copy<<<(NN * HH + 255) / 256, 256>>>(out);
}

// round 10
// speedup vs baseline: 3.1122x; 1.4679x over previous
#include <cuda_runtime.h>
#include <math.h>

#define NN 50000
#define EE 400000
#define EPP 40000
#define HH 128
#define LL 2
#define NB ((NN + 1023) / 1024)

// ---------------- scratch (device globals; no runtime allocation) ------------
__device__ __align__(16) float    g_x[(size_t)NN*HH];
__device__ __align__(16) float    g_n1[(size_t)NN*HH];
__device__ __align__(16) float    g_n2[(size_t)NN*HH];
__device__ __align__(16) float    g_agg[(size_t)NN*4*HH];
__device__ __align__(16) float    g_ea[(size_t)EE*HH];
__device__ __align__(16) float    g_eb1[(size_t)EE*HH];
__device__ float g_amp[NN];
__device__ float g_att[NN];
__device__ __align__(16) float g_W3[HH*HH];
__device__ __align__(16) float g_Wfold[13*HH*HH];
__device__ __align__(16) float g_bias1[HH];
__device__ __align__(16) float g_bias2[HH];
__device__ float g_bns[HH];
__device__ float g_bnq[HH];
// CSR
__device__ int g_degi[NN];
__device__ int g_rowptr[NN + 1];
__device__ int g_cursor[NN];
__device__ int g_blocksum[64];
__device__ int g_eperm[EE];
__device__ int g_srcs[EE];

// ---------------- helpers ----------------------------------------------------
__device__ __forceinline__ unsigned tf32r(float f) {
    unsigned u;
    asm("cvt.rna.tf32.f32 %0, %1;" : "=r"(u) : "f"(f));
    return u;
}
__device__ __forceinline__ uint4 tf32r4(float4 v) {
    uint4 o;
    o.x = tf32r(v.x); o.y = tf32r(v.y); o.z = tf32r(v.z); o.w = tf32r(v.w);
    return o;
}
__device__ __forceinline__ void mma_tf32(float* d, const unsigned* a, const unsigned* b) {
    asm volatile(
        "mma.sync.aligned.m16n8k8.row.col.f32.tf32.tf32.f32 "
        "{%0,%1,%2,%3}, {%4,%5,%6,%7}, {%8,%9}, {%0,%1,%2,%3};"
        : "+f"(d[0]), "+f"(d[1]), "+f"(d[2]), "+f"(d[3])
        : "r"(a[0]), "r"(a[1]), "r"(a[2]), "r"(a[3]), "r"(b[0]), "r"(b[1]));
}

// shared compute step: one 16-K chunk of the 128x128 block tile
__device__ __forceinline__ void tile_compute(
    const unsigned (*__restrict__ Asb)[20], const unsigned (*__restrict__ Bsb)[136],
    float acc[2][8][4], int wm, int wn, int gid, int tq)
{
#pragma unroll
    for (int kk = 0; kk < 16; kk += 8) {
        unsigned af[2][4];
#pragma unroll
        for (int mt = 0; mt < 2; mt++) {
            int r = wm + mt * 16 + gid;
            af[mt][0] = Asb[r][kk + tq];
            af[mt][1] = Asb[r + 8][kk + tq];
            af[mt][2] = Asb[r][kk + tq + 4];
            af[mt][3] = Asb[r + 8][kk + tq + 4];
        }
#pragma unroll
        for (int nt = 0; nt < 8; nt++) {
            unsigned bf[2];
            bf[0] = Bsb[kk + tq][wn + nt * 8 + gid];
            bf[1] = Bsb[kk + tq + 4][wn + nt * 8 + gid];
            mma_tf32(acc[0][nt], af[0], bf);
            mma_tf32(acc[1][nt], af[1], bf);
        }
    }
}

// ---------------- pipelined tf32 GEMM (optional A row gather) -----------------
// C[M,128] = alpha*A[idx(M),K]@B[K,128] + bscale*bias
__global__ __launch_bounds__(256, 2) void k_gemm_tc(
    const float* __restrict__ A, const float* __restrict__ B,
    const float* __restrict__ bias, float* __restrict__ C,
    const int* __restrict__ Aidx,
    int M, int K, float alpha, float bscale)
{
    __shared__ unsigned As[2][128][20];
    __shared__ unsigned Bs[2][16][136];
    const int t = threadIdx.x;
    const int m0 = blockIdx.x * 128;
    const int warp = t >> 5, lane = t & 31;
    const int gid = lane >> 2, tq = lane & 3;
    const int wm = (warp >> 1) * 32, wn = (warp & 1) * 64;

    const int rowA0 = t >> 2, rowA1 = 64 + (t >> 2);
    const int kq = (t & 3) * 4;
    const int kb0 = t >> 5, kb1 = 8 + (t >> 5);
    const int nq = (t & 31) * 4;
    const int gr0 = m0 + rowA0, gr1 = m0 + rowA1;
    const bool v0 = gr0 < M, v1 = gr1 < M;
    size_t ar0 = 0, ar1 = 0;
    if (v0) ar0 = (size_t)(Aidx ? __ldg(Aidx + gr0) : gr0) * K;
    if (v1) ar1 = (size_t)(Aidx ? __ldg(Aidx + gr1) : gr1) * K;

    float acc[2][8][4];
#pragma unroll
    for (int mt = 0; mt < 2; mt++)
#pragma unroll
        for (int nt = 0; nt < 8; nt++)
#pragma unroll
            for (int i = 0; i < 4; i++) acc[mt][nt][i] = 0.f;

    const float4 fz = make_float4(0.f, 0.f, 0.f, 0.f);
    float4 a0 = v0 ? *(const float4*)(A + ar0 + kq) : fz;
    float4 a1 = v1 ? *(const float4*)(A + ar1 + kq) : fz;
    float4 b0 = *(const float4*)(B + (size_t)kb0 * HH + nq);
    float4 b1 = *(const float4*)(B + (size_t)kb1 * HH + nq);
    *(uint4*)&As[0][rowA0][kq] = tf32r4(a0);
    *(uint4*)&As[0][rowA1][kq] = tf32r4(a1);
    *(uint4*)&Bs[0][kb0][nq] = tf32r4(b0);
    *(uint4*)&Bs[0][kb1][nq] = tf32r4(b1);
    __syncthreads();

    int cur = 0;
    for (int k0 = 16; k0 < K; k0 += 16) {
        a0 = v0 ? *(const float4*)(A + ar0 + k0 + kq) : fz;
        a1 = v1 ? *(const float4*)(A + ar1 + k0 + kq) : fz;
        b0 = *(const float4*)(B + (size_t)(k0 + kb0) * HH + nq);
        b1 = *(const float4*)(B + (size_t)(k0 + kb1) * HH + nq);
        tile_compute(As[cur], Bs[cur], acc, wm, wn, gid, tq);
        *(uint4*)&As[cur ^ 1][rowA0][kq] = tf32r4(a0);
        *(uint4*)&As[cur ^ 1][rowA1][kq] = tf32r4(a1);
        *(uint4*)&Bs[cur ^ 1][kb0][nq] = tf32r4(b0);
        *(uint4*)&Bs[cur ^ 1][kb1][nq] = tf32r4(b1);
        __syncthreads();
        cur ^= 1;
    }
    tile_compute(As[cur], Bs[cur], acc, wm, wn, gid, tq);

#pragma unroll
    for (int nt = 0; nt < 8; nt++) {
        int col = wn + nt * 8 + tq * 2;
        float bx = 0.f, by = 0.f;
        if (bias) { bx = bias[col] * bscale; by = bias[col + 1] * bscale; }
#pragma unroll
        for (int mt = 0; mt < 2; mt++) {
            int r0 = m0 + wm + mt * 16 + gid;
            int r1 = r0 + 8;
            if (r0 < M) {
                float2 o = make_float2(acc[mt][nt][0] * alpha + bx,
                                       acc[mt][nt][1] * alpha + by);
                *(float2*)(C + (size_t)r0 * HH + col) = o;
            }
            if (r1 < M) {
                float2 o = make_float2(acc[mt][nt][2] * alpha + bx,
                                       acc[mt][nt][3] * alpha + by);
                *(float2*)(C + (size_t)r1 * HH + col) = o;
            }
        }
    }
}

// ---------------- fused edge-update GEMM (pipelined):
// ea[e] += 0.5 * relu(n1[src[e]] + n2[dst[e]] + eb1[e] + b1) @ W2 + 0.5*b2
__global__ __launch_bounds__(256, 2) void k_gemm_upd_tc(
    const int* __restrict__ srcp, const int* __restrict__ dstp,
    const float* __restrict__ b1, const float* __restrict__ W2,
    const float* __restrict__ b2)
{
    __shared__ unsigned As[2][128][20];
    __shared__ unsigned Bs[2][16][136];
    const int t = threadIdx.x;
    const int m0 = blockIdx.x * 128;
    const int warp = t >> 5, lane = t & 31;
    const int gid = lane >> 2, tq = lane & 3;
    const int wm = (warp >> 1) * 32, wn = (warp & 1) * 64;

    const int rowA0 = t >> 2, rowA1 = 64 + (t >> 2);
    const int kq = (t & 3) * 4;
    const int kb0 = t >> 5, kb1 = 8 + (t >> 5);
    const int nq = (t & 31) * 4;
    const int e0 = m0 + rowA0, e1 = m0 + rowA1;
    const size_t s0 = (size_t)__ldg(srcp + e0) * HH, d0 = (size_t)__ldg(dstp + e0) * HH;
    const size_t s1 = (size_t)__ldg(srcp + e1) * HH, d1 = (size_t)__ldg(dstp + e1) * HH;

    float acc[2][8][4];
#pragma unroll
    for (int mt = 0; mt < 2; mt++)
#pragma unroll
        for (int nt = 0; nt < 8; nt++)
#pragma unroll
            for (int i = 0; i < 4; i++) acc[mt][nt][i] = 0.f;

    auto loadA = [&](size_t s, size_t d, int e, int kg) -> float4 {
        float4 p = *(const float4*)(g_n1 + s + kg);
        float4 q = *(const float4*)(g_n2 + d + kg);
        float4 w = *(const float4*)(g_eb1 + (size_t)e * HH + kg);
        float4 bb = *(const float4*)(b1 + kg);
        float4 o;
        o.x = fmaxf(p.x + q.x + w.x + bb.x, 0.f);
        o.y = fmaxf(p.y + q.y + w.y + bb.y, 0.f);
        o.z = fmaxf(p.z + q.z + w.z + bb.z, 0.f);
        o.w = fmaxf(p.w + q.w + w.w + bb.w, 0.f);
        return o;
    };

    float4 a0 = loadA(s0, d0, e0, kq);
    float4 a1 = loadA(s1, d1, e1, kq);
    float4 b0 = *(const float4*)(W2 + (size_t)kb0 * HH + nq);
    float4 b1v = *(const float4*)(W2 + (size_t)kb1 * HH + nq);
    *(uint4*)&As[0][rowA0][kq] = tf32r4(a0);
    *(uint4*)&As[0][rowA1][kq] = tf32r4(a1);
    *(uint4*)&Bs[0][kb0][nq] = tf32r4(b0);
    *(uint4*)&Bs[0][kb1][nq] = tf32r4(b1v);
    __syncthreads();

    int cur = 0;
    for (int k0 = 16; k0 < HH; k0 += 16) {
        a0 = loadA(s0, d0, e0, k0 + kq);
        a1 = loadA(s1, d1, e1, k0 + kq);
        b0 = *(const float4*)(W2 + (size_t)(k0 + kb0) * HH + nq);
        b1v = *(const float4*)(W2 + (size_t)(k0 + kb1) * HH + nq);
        tile_compute(As[cur], Bs[cur], acc, wm, wn, gid, tq);
        *(uint4*)&As[cur ^ 1][rowA0][kq] = tf32r4(a0);
        *(uint4*)&As[cur ^ 1][rowA1][kq] = tf32r4(a1);
        *(uint4*)&Bs[cur ^ 1][kb0][nq] = tf32r4(b0);
        *(uint4*)&Bs[cur ^ 1][kb1][nq] = tf32r4(b1v);
        __syncthreads();
        cur ^= 1;
    }
    tile_compute(As[cur], Bs[cur], acc, wm, wn, gid, tq);

#pragma unroll
    for (int nt = 0; nt < 8; nt++) {
        int col = wn + nt * 8 + tq * 2;
        float bx = b2[col] * 0.5f, by = b2[col + 1] * 0.5f;
#pragma unroll
        for (int mt = 0; mt < 2; mt++) {
            int r0 = m0 + wm + mt * 16 + gid;
            int r1 = r0 + 8;
            {
                float2 c = *(const float2*)(g_ea + (size_t)r0 * HH + col);
                float2 o = make_float2(acc[mt][nt][0] * 0.5f + bx + c.x,
                                       acc[mt][nt][1] * 0.5f + by + c.y);
                *(float2*)(g_ea + (size_t)r0 * HH + col) = o;
            }
            {
                float2 c = *(const float2*)(g_ea + (size_t)r1 * HH + col);
                float2 o = make_float2(acc[mt][nt][2] * 0.5f + bx + c.x,
                                       acc[mt][nt][3] * 0.5f + by + c.y);
                *(float2*)(g_ea + (size_t)r1 * HH + col) = o;
            }
        }
    }
}

// ---------------- fused post+lin on tensor cores (pipelined) ------------------
__global__ __launch_bounds__(256, 2) void k_post_tc()
{
    __shared__ unsigned As[2][128][20];
    __shared__ unsigned Bs[2][16][136];
    const int t = threadIdx.x;
    const int m0 = blockIdx.x * 128;
    const int warp = t >> 5, lane = t & 31;
    const int gid = lane >> 2, tq = lane & 3;
    const int wm = (warp >> 1) * 32, wn = (warp & 1) * 64;
    const int K = 13 * HH;

    const int rowA0 = t >> 2, rowA1 = 64 + (t >> 2);
    const int kq = (t & 3) * 4;
    const int kb0 = t >> 5, kb1 = 8 + (t >> 5);
    const int nq = (t & 31) * 4;
    const int gr0 = m0 + rowA0, gr1 = m0 + rowA1;
    const bool v0 = gr0 < NN, v1 = gr1 < NN;
    const float amp0 = v0 ? g_amp[gr0] : 0.f, att0 = v0 ? g_att[gr0] : 0.f;
    const float amp1 = v1 ? g_amp[gr1] : 0.f, att1 = v1 ? g_att[gr1] : 0.f;

    float acc[2][8][4];
#pragma unroll
    for (int mt = 0; mt < 2; mt++)
#pragma unroll
        for (int nt = 0; nt < 8; nt++)
#pragma unroll
            for (int i = 0; i < 4; i++) acc[mt][nt][i] = 0.f;

    auto loadA = [&](int gr, bool valid, float amp, float att, int kg) -> float4 {
        if (!valid) return make_float4(0.f, 0.f, 0.f, 0.f);
        if (kg < HH) return *(const float4*)(g_x + (size_t)gr * HH + kg);
        int kk = kg - HH;
        int sec = kk >> 9, j = kk & 511;
        float4 av = *(const float4*)(g_agg + (size_t)gr * 512 + j);
        if (sec != 0) {
            float s = (sec == 1) ? amp : att;
            av.x *= s; av.y *= s; av.z *= s; av.w *= s;
        }
        return av;
    };

    float4 a0 = loadA(gr0, v0, amp0, att0, kq);
    float4 a1 = loadA(gr1, v1, amp1, att1, kq);
    float4 b0 = *(const float4*)(g_Wfold + (size_t)kb0 * HH + nq);
    float4 b1 = *(const float4*)(g_Wfold + (size_t)kb1 * HH + nq);
    *(uint4*)&As[0][rowA0][kq] = tf32r4(a0);
    *(uint4*)&As[0][rowA1][kq] = tf32r4(a1);
    *(uint4*)&Bs[0][kb0][nq] = tf32r4(b0);
    *(uint4*)&Bs[0][kb1][nq] = tf32r4(b1);
    __syncthreads();

    int cur = 0;
    for (int k0 = 16; k0 < K; k0 += 16) {
        a0 = loadA(gr0, v0, amp0, att0, k0 + kq);
        a1 = loadA(gr1, v1, amp1, att1, k0 + kq);
        b0 = *(const float4*)(g_Wfold + (size_t)(k0 + kb0) * HH + nq);
        b1 = *(const float4*)(g_Wfold + (size_t)(k0 + kb1) * HH + nq);
        tile_compute(As[cur], Bs[cur], acc, wm, wn, gid, tq);
        *(uint4*)&As[cur ^ 1][rowA0][kq] = tf32r4(a0);
        *(uint4*)&As[cur ^ 1][rowA1][kq] = tf32r4(a1);
        *(uint4*)&Bs[cur ^ 1][kb0][nq] = tf32r4(b0);
        *(uint4*)&Bs[cur ^ 1][kb1][nq] = tf32r4(b1);
        __syncthreads();
        cur ^= 1;
    }
    tile_compute(As[cur], Bs[cur], acc, wm, wn, gid, tq);

#pragma unroll
    for (int nt = 0; nt < 8; nt++) {
        int col = wn + nt * 8 + tq * 2;
        float bx = g_bias2[col], by = g_bias2[col + 1];
#pragma unroll
        for (int mt = 0; mt < 2; mt++) {
            int r0 = m0 + wm + mt * 16 + gid;
            int r1 = r0 + 8;
            if (r0 < NN) {
                float2 o = make_float2(acc[mt][nt][0] + bx, acc[mt][nt][1] + by);
                *(float2*)(g_n1 + (size_t)r0 * HH + col) = o;
            }
            if (r1 < NN) {
                float2 o = make_float2(acc[mt][nt][2] + bx, acc[mt][nt][3] + by);
                *(float2*)(g_n1 + (size_t)r1 * HH + col) = o;
            }
        }
    }
}

// ---------------- exact fp32 SIMT GEMM (tiny weight folds) --------------------
__global__ __launch_bounds__(256) void k_gemm(
    const float* __restrict__ A, const float* __restrict__ B,
    float* __restrict__ C, int M, int K)
{
    __shared__ float As[64][16];
    __shared__ float Bs[16][128];
    const int t = threadIdx.x;
    const int m0 = blockIdx.x * 64;
    const int lane = t & 31;
    const int wrow = (t >> 5) * 8;
    const int col0 = lane * 4;
    const int ar = t >> 2;
    const int ak = (t & 3) * 4;
    const int br = t >> 4;
    const int bc = (t & 15) * 8;

    float acc[8][4];
#pragma unroll
    for (int i = 0; i < 8; i++) { acc[i][0]=0.f; acc[i][1]=0.f; acc[i][2]=0.f; acc[i][3]=0.f; }

    for (int k0 = 0; k0 < K; k0 += 16) {
        float4 av = make_float4(0.f,0.f,0.f,0.f);
        int grow = m0 + ar;
        if (grow < M) av = *(const float4*)(A + (size_t)grow * K + k0 + ak);
        *(float4*)&As[ar][ak] = av;
        *(float4*)&Bs[br][bc]     = *(const float4*)(B + (size_t)(k0 + br) * HH + bc);
        *(float4*)&Bs[br][bc + 4] = *(const float4*)(B + (size_t)(k0 + br) * HH + bc + 4);
        __syncthreads();
#pragma unroll
        for (int k = 0; k < 16; k++) {
            float4 b = *(const float4*)&Bs[k][col0];
#pragma unroll
            for (int i = 0; i < 8; i++) {
                float a = As[wrow + i][k];
                acc[i][0] = fmaf(a, b.x, acc[i][0]);
                acc[i][1] = fmaf(a, b.y, acc[i][1]);
                acc[i][2] = fmaf(a, b.z, acc[i][2]);
                acc[i][3] = fmaf(a, b.w, acc[i][3]);
            }
        }
        __syncthreads();
    }
#pragma unroll
    for (int i = 0; i < 8; i++) {
        int r = m0 + wrow + i;
        if (r < M) {
            float4 o = make_float4(acc[i][0], acc[i][1], acc[i][2], acc[i][3]);
            *(float4*)(C + (size_t)r * HH + col0) = o;
        }
    }
}

// ---------------- CSR build ---------------------------------------------------
__global__ void k_zeroi(int* p, int n) {
    int i = blockIdx.x * blockDim.x + threadIdx.x;
    if (i < n) p[i] = 0;
}
__global__ void k_degacc(const int* __restrict__ dst) {
    int i = blockIdx.x * blockDim.x + threadIdx.x;
    if (i < EE) atomicAdd(&g_degi[dst[i]], 1);
}
__global__ __launch_bounds__(1024) void k_scan1() {
    __shared__ int sh[1024];
    int i = blockIdx.x * 1024 + threadIdx.x;
    int v = (i < NN) ? g_degi[i] : 0;
    sh[threadIdx.x] = v;
    __syncthreads();
    for (int off = 1; off < 1024; off <<= 1) {
        int tv = (threadIdx.x >= off) ? sh[threadIdx.x - off] : 0;
        __syncthreads();
        sh[threadIdx.x] += tv;
        __syncthreads();
    }
    if (i < NN) g_rowptr[i + 1] = sh[threadIdx.x];
    if (threadIdx.x == 1023) g_blocksum[blockIdx.x] = sh[1023];
}
__global__ void k_scan2() {
    if (threadIdx.x == 0) {
        int s = 0;
        for (int b = 0; b < NB; b++) { int v = g_blocksum[b]; g_blocksum[b] = s; s += v; }
    }
}
__global__ __launch_bounds__(1024) void k_scan3() {
    int i = blockIdx.x * 1024 + threadIdx.x;
    if (i < NN) g_rowptr[i + 1] += g_blocksum[i >> 10];
    if (i == 0) g_rowptr[0] = 0;
}
__global__ void k_cursor() {
    int i = blockIdx.x * blockDim.x + threadIdx.x;
    if (i < NN) g_cursor[i] = g_rowptr[i];
}
__global__ void k_scatter(const int* __restrict__ src, const int* __restrict__ dst) {
    int e = blockIdx.x * blockDim.x + threadIdx.x;
    if (e >= EE) return;
    int d = dst[e];
    int p = atomicAdd(&g_cursor[d], 1);
    g_eperm[p] = e;
    g_srcs[p] = src[e];
}

// ---------------- small kernels ----------------------------------------------
__global__ void k_nodestats(const float* __restrict__ adl_p) {
    int n = blockIdx.x * blockDim.x + threadIdx.x;
    if (n >= NN) return;
    float adl = __ldg(adl_p);
    float d = (float)(g_rowptr[n + 1] - g_rowptr[n]);
    float degc = fmaxf(d, 1.0f);
    float lg = logf(degc + 1.0f);
    g_amp[n] = lg / adl;
    g_att[n] = adl / lg;
}

__global__ void k_vecmat(const float* __restrict__ v, const float* __restrict__ W,
                         const float* __restrict__ b0, float* __restrict__ out) {
    int j = threadIdx.x;
    float s = b0[j];
    for (int k = 0; k < HH; k++) s = fmaf(v[k], W[k * HH + j], s);
    out[j] = s;
}

// CSR aggregation: one warp per node, registers only, no atomics.
__global__ __launch_bounds__(256) void k_msg_csr() {
    int n = blockIdx.x * 8 + (threadIdx.x >> 5);
    if (n >= NN) return;
    int lane = threadIdx.x & 31;
    int c = lane * 4;
    float4 bb = *(const float4*)(g_bias1 + c);
    float4 xd = *(const float4*)(g_n1 + (size_t)n * HH + c);
    float cx = xd.x + bb.x, cy = xd.y + bb.y, cz = xd.z + bb.z, cw = xd.w + bb.w;
    int beg = g_rowptr[n], end = g_rowptr[n + 1];
    float s1x = 0.f, s1y = 0.f, s1z = 0.f, s1w = 0.f;
    float s2x = 0.f, s2y = 0.f, s2z = 0.f, s2w = 0.f;
    float mnx = INFINITY, mny = INFINITY, mnz = INFINITY, mnw = INFINITY;
    float mxx = -INFINITY, mxy = -INFINITY, mxz = -INFINITY, mxw = -INFINITY;
    for (int i = beg; i < end; i++) {
        int s = __ldg(g_srcs + i);
        float4 b = *(const float4*)(g_n2 + (size_t)s * HH + c);
        float4 w = *(const float4*)(g_eb1 + (size_t)i * HH + c);
        float hx = cx + b.x + w.x;
        float hy = cy + b.y + w.y;
        float hz = cz + b.z + w.z;
        float hw = cw + b.w + w.w;
        s1x += hx; s1y += hy; s1z += hz; s1w += hw;
        s2x = fmaf(hx, hx, s2x); s2y = fmaf(hy, hy, s2y);
        s2z = fmaf(hz, hz, s2z); s2w = fmaf(hw, hw, s2w);
        mnx = fminf(mnx, hx); mny = fminf(mny, hy); mnz = fminf(mnz, hz); mnw = fminf(mnw, hw);
        mxx = fmaxf(mxx, hx); mxy = fmaxf(mxy, hy); mxz = fmaxf(mxz, hz); mxw = fmaxf(mxw, hw);
    }
    int deg = end - beg;
    float dinv = (deg > 0) ? (1.0f / (float)deg) : 1.0f;
    if (deg == 0) {
        s1x = s1y = s1z = s1w = 0.f;
        s2x = s2y = s2z = s2w = 0.f;
        mnx = mny = mnz = mnw = 0.f;
        mxx = mxy = mxz = mxw = 0.f;
    }
    float mex = s1x * dinv, mey = s1y * dinv, mez = s1z * dinv, mew = s1w * dinv;
    float sdx = sqrtf(fmaxf(s2x * dinv - mex * mex, 0.f) + 1e-5f);
    float sdy = sqrtf(fmaxf(s2y * dinv - mey * mey, 0.f) + 1e-5f);
    float sdz = sqrtf(fmaxf(s2z * dinv - mez * mez, 0.f) + 1e-5f);
    float sdw = sqrtf(fmaxf(s2w * dinv - mew * mew, 0.f) + 1e-5f);
    size_t bse = (size_t)n * 512;
    *(float4*)(g_agg + bse + c)       = make_float4(mex, mey, mez, mew);
    *(float4*)(g_agg + bse + 128 + c) = make_float4(mnx, mny, mnz, mnw);
    *(float4*)(g_agg + bse + 256 + c) = make_float4(mxx, mxy, mxz, mxw);
    *(float4*)(g_agg + bse + 384 + c) = make_float4(sdx, sdy, sdz, sdw);
}

__global__ void k_bnzero() {
    int t = threadIdx.x;
    g_bns[t] = 0.f;
    g_bnq[t] = 0.f;
}

__global__ __launch_bounds__(256) void k_bnred() {
    __shared__ float sh[256], shq[256];
    int t = threadIdx.x;
    int col = t & 127;
    int half = t >> 7;
    float s = 0.f, q = 0.f;
    for (int row = blockIdx.x * 2 + half; row < NN; row += gridDim.x * 2) {
        float v = g_n1[(size_t)row * HH + col];
        s += v; q += v * v;
    }
    sh[t] = s; shq[t] = q;
    __syncthreads();
    if (half == 0) {
        atomicAdd(&g_bns[col], s + sh[t + 128]);
        atomicAdd(&g_bnq[col], q + shq[t + 128]);
    }
}

// BN + residual; optionally mirrors the result into `extra` (final output)
__global__ void k_bnapply(const float* __restrict__ gamma, const float* __restrict__ beta,
                          float* __restrict__ extra) {
    int i = blockIdx.x * blockDim.x + threadIdx.x;
    if (i >= NN * HH) return;
    int c = i & 127;
    const float invN = 1.0f / (float)NN;
    float mu = g_bns[c] * invN;
    float var = g_bnq[c] * invN - mu * mu;
    float v = g_n1[i];
    float bn = gamma[c] * (v - mu) * rsqrtf(var + 1e-5f) + beta[c];
    float r = (g_x[i] + fmaxf(bn, 0.f)) * 0.5f;
    g_x[i] = r;
    if (extra) extra[i] = r;
}

// ---------------- host orchestration -----------------------------------------
extern "C" void kernel_launch(void* const* d_in, const int* in_sizes, int n_in,
                              void* d_out, int out_size) {
    const float* x_in   = (const float*)d_in[0];
    const int*   ei     = (const int*)d_in[1];
    const float* eattr  = (const float*)d_in[2];
    const float* pattr  = (const float*)d_in[4];
    const float* nattr  = (const float*)d_in[6];
    const float* adl    = (const float*)d_in[7];
    const float* node_w = (const float*)d_in[8];
    const float* node_b = (const float*)d_in[9];
    const float* edge_w = (const float*)d_in[10];
    const float* edge_b = (const float*)d_in[11];
    const float* eenc_w = (const float*)d_in[12];
    const float* eenc_b = (const float*)d_in[13];
    const float* pre_w  = (const float*)d_in[14];
    const float* pre_b  = (const float*)d_in[15];
    const float* post_w = (const float*)d_in[16];
    const float* post_b = (const float*)d_in[17];
    const float* lin_w  = (const float*)d_in[18];
    const float* lin_b  = (const float*)d_in[19];
    const float* ew1    = (const float*)d_in[20];
    const float* eb1v   = (const float*)d_in[21];
    const float* ew2    = (const float*)d_in[22];
    const float* eb2v   = (const float*)d_in[23];
    const float* bng    = (const float*)d_in[24];
    const float* bnb    = (const float*)d_in[25];
    float* out = (float*)d_out;

    float *p_x, *p_ea, *p_n1, *p_n2, *p_eb1, *p_W3, *p_Wfold, *p_b1, *p_b2;
    int *p_degi, *p_eperm;
    cudaGetSymbolAddress((void**)&p_x, g_x);
    cudaGetSymbolAddress((void**)&p_ea, g_ea);
    cudaGetSymbolAddress((void**)&p_n1, g_n1);
    cudaGetSymbolAddress((void**)&p_n2, g_n2);
    cudaGetSymbolAddress((void**)&p_eb1, g_eb1);
    cudaGetSymbolAddress((void**)&p_W3, g_W3);
    cudaGetSymbolAddress((void**)&p_Wfold, g_Wfold);
    cudaGetSymbolAddress((void**)&p_b1, g_bias1);
    cudaGetSymbolAddress((void**)&p_b2, g_bias2);
    cudaGetSymbolAddress((void**)&p_degi, g_degi);
    cudaGetSymbolAddress((void**)&p_eperm, g_eperm);

    const int* src = ei;
    const int* dst = ei + EE;

    auto gemm = [](const float* A, const float* B, const float* bias, float* C,
                   const int* Aidx, int M, int K, float alpha, float bscale) {
        k_gemm_tc<<<(M + 127) / 128, 256>>>(A, B, bias, C, Aidx, M, K, alpha, bscale);
    };

    // ---- CSR build (once) ----
    k_zeroi<<<(NN + 255) / 256, 256>>>(p_degi, NN);
    k_degacc<<<(EE + 255) / 256, 256>>>(dst);
    k_scan1<<<NB, 1024>>>();
    k_scan2<<<1, 32>>>();
    k_scan3<<<NB, 1024>>>();
    k_cursor<<<(NN + 255) / 256, 256>>>();
    k_scatter<<<(EE + 255) / 256, 256>>>(src, dst);
    k_nodestats<<<(NN + 255) / 256, 256>>>(adl);

    // ---- embeddings ----
    gemm(x_in, node_w, node_b, p_x, nullptr, NN, 64, 1.f, 1.f);
    gemm(eattr, edge_w, edge_b, p_ea, nullptr, EE, 32, 1.f, 1.f);
    gemm(pattr, edge_w, edge_b, out + (size_t)NN * HH, nullptr, EPP, 32, 1.f, 1.f);
    gemm(nattr, edge_w, edge_b, out + (size_t)NN * HH + (size_t)EPP * HH, nullptr, EPP, 32, 1.f, 1.f);

    for (int l = 0; l < LL; l++) {
        const float* preW = pre_w + (size_t)l * 384 * HH;
        const float* postW = post_w + (size_t)l * 1664 * HH;
        const float* linW = lin_w + (size_t)l * HH * HH;
        const float* e1W = ew1 + (size_t)l * 384 * HH;
        const float* e2W = ew2 + (size_t)l * HH * HH;
        const bool last = (l == LL - 1);

        // weight/bias folds (exact fp32) — grid must cover all M rows (64/block)
        k_gemm<<<(HH + 63) / 64, 256>>>(eenc_w + (size_t)l * HH * HH, preW + 256 * HH, p_W3, HH, HH);
        k_vecmat<<<1, 128>>>(eenc_b + l * HH, preW + 256 * HH, pre_b + l * HH, p_b1);
        k_gemm<<<(13 * HH + 63) / 64, 256>>>(postW, linW, p_Wfold, 13 * HH, HH);
        k_vecmat<<<1, 128>>>(post_b + l * HH, linW, lin_b + l * HH, p_b2);

        // message projections
        gemm(p_x, preW, nullptr, p_n1, nullptr, NN, HH, 1.f, 1.f);            // x@P0 (dst)
        gemm(p_x, preW + 128 * HH, nullptr, p_n2, nullptr, NN, HH, 1.f, 1.f); // x@P1 (src)
        gemm(p_ea, p_W3, nullptr, p_eb1, p_eperm, EE, HH, 1.f, 1.f);          // dst-sorted eb1

        // aggregate (no atomics)
        k_msg_csr<<<(NN + 7) / 8, 256>>>();

        // node update: fused post+lin, then BN + residual
        k_post_tc<<<(NN + 127) / 128, 256>>>();
        k_bnzero<<<1, 128>>>();
        k_bnred<<<256, 256>>>();
        k_bnapply<<<(NN * HH + 255) / 256, 256>>>(bng + l * HH, bnb + l * HH,
                                                  last ? out : nullptr);

        // edge update — DEAD on the last layer (ea never read again); skip it
        if (!last) {
            gemm(p_x, e1W, nullptr, p_n1, nullptr, NN, HH, 1.f, 1.f);            // x@U0 (src)
            gemm(p_x, e1W + 128 * HH, nullptr, p_n2, nullptr, NN, HH, 1.f, 1.f); // x@U1 (dst)
            gemm(p_ea, e1W + 256 * HH, nullptr, p_eb1, nullptr, EE, HH, 1.f, 1.f);
            k_gemm_upd_tc<<<EE / 128, 256>>>(src, dst, eb1v + l * HH, e2W, eb2v + l * HH);
        }
    }
}

// round 11
// speedup vs baseline: 3.1975x; 1.0274x over previous
#include <cuda_runtime.h>
#include <math.h>

#define NN 50000
#define EE 400000
#define EPP 40000
#define HH 128
#define LL 2
#define NB ((NN + 1023) / 1024)

// ---------------- scratch (device globals; no runtime allocation) ------------
__device__ __align__(16) float    g_x[(size_t)NN*HH];
__device__ __align__(16) float    g_n1[(size_t)NN*HH];
__device__ __align__(16) float    g_n2[(size_t)NN*HH];
__device__ __align__(16) float    g_agg[(size_t)NN*4*HH];
__device__ __align__(16) float    g_ea[(size_t)EE*HH];
__device__ __align__(16) float    g_eb1[(size_t)EE*HH];
__device__ float g_amp[NN];
__device__ float g_att[NN];
__device__ __align__(16) float g_W3[2*HH*HH];
__device__ __align__(16) float g_Wfold[2*13*HH*HH];
__device__ __align__(16) float g_bias1[2*HH];
__device__ __align__(16) float g_bias2[2*HH];
__device__ float g_bns[HH];
__device__ float g_bnq[HH];
// CSR
__device__ int g_degi[NN];
__device__ int g_rowptr[NN + 1];
__device__ int g_cursor[NN];
__device__ int g_blocksum[64];
__device__ int g_eperm[EE];
__device__ int g_srcs[EE];

// ---------------- helpers ----------------------------------------------------
__device__ __forceinline__ unsigned tf32r(float f) {
    unsigned u;
    asm("cvt.rna.tf32.f32 %0, %1;" : "=r"(u) : "f"(f));
    return u;
}
__device__ __forceinline__ uint4 tf32r4(float4 v) {
    uint4 o;
    o.x = tf32r(v.x); o.y = tf32r(v.y); o.z = tf32r(v.z); o.w = tf32r(v.w);
    return o;
}
__device__ __forceinline__ void mma_tf32(float* d, const unsigned* a, const unsigned* b) {
    asm volatile(
        "mma.sync.aligned.m16n8k8.row.col.f32.tf32.tf32.f32 "
        "{%0,%1,%2,%3}, {%4,%5,%6,%7}, {%8,%9}, {%0,%1,%2,%3};"
        : "+f"(d[0]), "+f"(d[1]), "+f"(d[2]), "+f"(d[3])
        : "r"(a[0]), "r"(a[1]), "r"(a[2]), "r"(a[3]), "r"(b[0]), "r"(b[1]));
}

// shared compute step: one 16-K chunk of the 128x128 block tile
__device__ __forceinline__ void tile_compute(
    const unsigned (*__restrict__ Asb)[20], const unsigned (*__restrict__ Bsb)[136],
    float acc[2][8][4], int wm, int wn, int gid, int tq)
{
#pragma unroll
    for (int kk = 0; kk < 16; kk += 8) {
        unsigned af[2][4];
#pragma unroll
        for (int mt = 0; mt < 2; mt++) {
            int r = wm + mt * 16 + gid;
            af[mt][0] = Asb[r][kk + tq];
            af[mt][1] = Asb[r + 8][kk + tq];
            af[mt][2] = Asb[r][kk + tq + 4];
            af[mt][3] = Asb[r + 8][kk + tq + 4];
        }
#pragma unroll
        for (int nt = 0; nt < 8; nt++) {
            unsigned bf[2];
            bf[0] = Bsb[kk + tq][wn + nt * 8 + gid];
            bf[1] = Bsb[kk + tq + 4][wn + nt * 8 + gid];
            mma_tf32(acc[0][nt], af[0], bf);
            mma_tf32(acc[1][nt], af[1], bf);
        }
    }
}

// A-fragments from a full-width 128x132 smem panel (Pf)
__device__ __forceinline__ void tile_compute_pf(
    const unsigned (*__restrict__ Pf)[132], const unsigned (*__restrict__ Bsb)[136],
    float acc[2][8][4], int kbase, int wm, int wn, int gid, int tq)
{
#pragma unroll
    for (int kk = 0; kk < 16; kk += 8) {
        unsigned af[2][4];
#pragma unroll
        for (int mt = 0; mt < 2; mt++) {
            int r = wm + mt * 16 + gid;
            af[mt][0] = Pf[r][kbase + kk + tq];
            af[mt][1] = Pf[r + 8][kbase + kk + tq];
            af[mt][2] = Pf[r][kbase + kk + tq + 4];
            af[mt][3] = Pf[r + 8][kbase + kk + tq + 4];
        }
#pragma unroll
        for (int nt = 0; nt < 8; nt++) {
            unsigned bf[2];
            bf[0] = Bsb[kk + tq][wn + nt * 8 + gid];
            bf[1] = Bsb[kk + tq + 4][wn + nt * 8 + gid];
            mma_tf32(acc[0][nt], af[0], bf);
            mma_tf32(acc[1][nt], af[1], bf);
        }
    }
}

// ---------------- pipelined tf32 GEMM (optional A row gather) -----------------
// C[M,128] = alpha*A[idx(M),K]@B[K,128] + bscale*bias
__global__ __launch_bounds__(256, 2) void k_gemm_tc(
    const float* __restrict__ A, const float* __restrict__ B,
    const float* __restrict__ bias, float* __restrict__ C,
    const int* __restrict__ Aidx,
    int M, int K, float alpha, float bscale)
{
    __shared__ unsigned As[2][128][20];
    __shared__ unsigned Bs[2][16][136];
    const int t = threadIdx.x;
    const int m0 = blockIdx.x * 128;
    const int warp = t >> 5, lane = t & 31;
    const int gid = lane >> 2, tq = lane & 3;
    const int wm = (warp >> 1) * 32, wn = (warp & 1) * 64;

    const int rowA0 = t >> 2, rowA1 = 64 + (t >> 2);
    const int kq = (t & 3) * 4;
    const int kb0 = t >> 5, kb1 = 8 + (t >> 5);
    const int nq = (t & 31) * 4;
    const int gr0 = m0 + rowA0, gr1 = m0 + rowA1;
    const bool v0 = gr0 < M, v1 = gr1 < M;
    size_t ar0 = 0, ar1 = 0;
    if (v0) ar0 = (size_t)(Aidx ? __ldg(Aidx + gr0) : gr0) * K;
    if (v1) ar1 = (size_t)(Aidx ? __ldg(Aidx + gr1) : gr1) * K;

    float acc[2][8][4];
#pragma unroll
    for (int mt = 0; mt < 2; mt++)
#pragma unroll
        for (int nt = 0; nt < 8; nt++)
#pragma unroll
            for (int i = 0; i < 4; i++) acc[mt][nt][i] = 0.f;

    const float4 fz = make_float4(0.f, 0.f, 0.f, 0.f);
    float4 a0 = v0 ? *(const float4*)(A + ar0 + kq) : fz;
    float4 a1 = v1 ? *(const float4*)(A + ar1 + kq) : fz;
    float4 b0 = *(const float4*)(B + (size_t)kb0 * HH + nq);
    float4 b1 = *(const float4*)(B + (size_t)kb1 * HH + nq);
    *(uint4*)&As[0][rowA0][kq] = tf32r4(a0);
    *(uint4*)&As[0][rowA1][kq] = tf32r4(a1);
    *(uint4*)&Bs[0][kb0][nq] = tf32r4(b0);
    *(uint4*)&Bs[0][kb1][nq] = tf32r4(b1);
    __syncthreads();

    int cur = 0;
    for (int k0 = 16; k0 < K; k0 += 16) {
        a0 = v0 ? *(const float4*)(A + ar0 + k0 + kq) : fz;
        a1 = v1 ? *(const float4*)(A + ar1 + k0 + kq) : fz;
        b0 = *(const float4*)(B + (size_t)(k0 + kb0) * HH + nq);
        b1 = *(const float4*)(B + (size_t)(k0 + kb1) * HH + nq);
        tile_compute(As[cur], Bs[cur], acc, wm, wn, gid, tq);
        *(uint4*)&As[cur ^ 1][rowA0][kq] = tf32r4(a0);
        *(uint4*)&As[cur ^ 1][rowA1][kq] = tf32r4(a1);
        *(uint4*)&Bs[cur ^ 1][kb0][nq] = tf32r4(b0);
        *(uint4*)&Bs[cur ^ 1][kb1][nq] = tf32r4(b1);
        __syncthreads();
        cur ^= 1;
    }
    tile_compute(As[cur], Bs[cur], acc, wm, wn, gid, tq);

#pragma unroll
    for (int nt = 0; nt < 8; nt++) {
        int col = wn + nt * 8 + tq * 2;
        float bx = 0.f, by = 0.f;
        if (bias) { bx = bias[col] * bscale; by = bias[col + 1] * bscale; }
#pragma unroll
        for (int mt = 0; mt < 2; mt++) {
            int r0 = m0 + wm + mt * 16 + gid;
            int r1 = r0 + 8;
            if (r0 < M) {
                float2 o = make_float2(acc[mt][nt][0] * alpha + bx,
                                       acc[mt][nt][1] * alpha + by);
                *(float2*)(C + (size_t)r0 * HH + col) = o;
            }
            if (r1 < M) {
                float2 o = make_float2(acc[mt][nt][2] * alpha + bx,
                                       acc[mt][nt][3] * alpha + by);
                *(float2*)(C + (size_t)r1 * HH + col) = o;
            }
        }
    }
}

// ---------------- FUSED edge update (two chained GEMMs, one kernel):
// P  = ea_tile @ U2
// H  = relu(P + n1[src] + n2[dst] + b1)       (epilogue -> smem panel, tf32)
// ea += 0.5 * (H @ W2) + 0.5 * b2
// dynamic smem: Pf[128][132] | As1[2][128][20] | Bs[2][16][136]  = 105472 B
__global__ __launch_bounds__(256, 2) void k_upd_fused(
    const int* __restrict__ srcp, const int* __restrict__ dstp,
    const float* __restrict__ U2, const float* __restrict__ b1,
    const float* __restrict__ W2, const float* __restrict__ b2)
{
    extern __shared__ unsigned smu[];
    unsigned (*Pf)[132] = reinterpret_cast<unsigned(*)[132]>(smu);
    unsigned* AsBase = smu + 128 * 132;
    unsigned* BsBase = AsBase + 2 * 128 * 20;
    auto AS = [&](int b) { return reinterpret_cast<unsigned(*)[20]>(AsBase + b * 2560); };
    auto BS = [&](int b) { return reinterpret_cast<unsigned(*)[136]>(BsBase + b * 2176); };

    const int t = threadIdx.x;
    const int m0 = blockIdx.x * 128;
    const int warp = t >> 5, lane = t & 31;
    const int gid = lane >> 2, tq = lane & 3;
    const int wm = (warp >> 1) * 32, wn = (warp & 1) * 64;

    const int rowA0 = t >> 2, rowA1 = 64 + (t >> 2);
    const int kq = (t & 3) * 4;
    const int kb0 = t >> 5, kb1 = 8 + (t >> 5);
    const int nq = (t & 31) * 4;

    float acc[2][8][4];
#pragma unroll
    for (int mt = 0; mt < 2; mt++)
#pragma unroll
        for (int nt = 0; nt < 8; nt++)
#pragma unroll
            for (int i = 0; i < 4; i++) acc[mt][nt][i] = 0.f;

    // ---- stage 1: P = ea_tile @ U2 (K = 128), pipelined ----
    const size_t arow0 = (size_t)(m0 + rowA0) * HH;
    const size_t arow1 = (size_t)(m0 + rowA1) * HH;
    float4 a0 = *(const float4*)(g_ea + arow0 + kq);
    float4 a1 = *(const float4*)(g_ea + arow1 + kq);
    float4 w0 = *(const float4*)(U2 + (size_t)kb0 * HH + nq);
    float4 w1 = *(const float4*)(U2 + (size_t)kb1 * HH + nq);
    *(uint4*)&AS(0)[rowA0][kq] = tf32r4(a0);
    *(uint4*)&AS(0)[rowA1][kq] = tf32r4(a1);
    *(uint4*)&BS(0)[kb0][nq] = tf32r4(w0);
    *(uint4*)&BS(0)[kb1][nq] = tf32r4(w1);
    __syncthreads();

    int cur = 0;
    for (int k0 = 16; k0 < HH; k0 += 16) {
        a0 = *(const float4*)(g_ea + arow0 + k0 + kq);
        a1 = *(const float4*)(g_ea + arow1 + k0 + kq);
        w0 = *(const float4*)(U2 + (size_t)(k0 + kb0) * HH + nq);
        w1 = *(const float4*)(U2 + (size_t)(k0 + kb1) * HH + nq);
        tile_compute(AS(cur), BS(cur), acc, wm, wn, gid, tq);
        *(uint4*)&AS(cur ^ 1)[rowA0][kq] = tf32r4(a0);
        *(uint4*)&AS(cur ^ 1)[rowA1][kq] = tf32r4(a1);
        *(uint4*)&BS(cur ^ 1)[kb0][nq] = tf32r4(w0);
        *(uint4*)&BS(cur ^ 1)[kb1][nq] = tf32r4(w1);
        __syncthreads();
        cur ^= 1;
    }
    tile_compute(AS(cur), BS(cur), acc, wm, wn, gid, tq);

    // ---- epilogue 1: H = relu(P + n1[src] + n2[dst] + b1) -> Pf (tf32) ----
    {
        int R[4] = {wm + gid, wm + gid + 8, wm + 16 + gid, wm + 24 + gid};
        size_t S[4], D[4];
#pragma unroll
        for (int j = 0; j < 4; j++) {
            S[j] = (size_t)__ldg(srcp + m0 + R[j]) * HH;
            D[j] = (size_t)__ldg(dstp + m0 + R[j]) * HH;
        }
#pragma unroll
        for (int nt = 0; nt < 8; nt++) {
            int col = wn + nt * 8 + tq * 2;
            float2 bb = *(const float2*)(b1 + col);
#pragma unroll
            for (int mt = 0; mt < 2; mt++) {
#pragma unroll
                for (int h = 0; h < 2; h++) {
                    int j = mt * 2 + h;
                    float2 u = *(const float2*)(g_n1 + S[j] + col);
                    float2 v = *(const float2*)(g_n2 + D[j] + col);
                    float hx = fmaxf(acc[mt][nt][h * 2 + 0] + u.x + v.x + bb.x, 0.f);
                    float hy = fmaxf(acc[mt][nt][h * 2 + 1] + u.y + v.y + bb.y, 0.f);
                    uint2 pw;
                    pw.x = tf32r(hx);
                    pw.y = tf32r(hy);
                    *(uint2*)&Pf[R[j]][col] = pw;
                }
            }
        }
    }

    // ---- stage 2: acc = H @ W2, A from Pf (full panel in smem) ----
#pragma unroll
    for (int mt = 0; mt < 2; mt++)
#pragma unroll
        for (int nt = 0; nt < 8; nt++)
#pragma unroll
            for (int i = 0; i < 4; i++) acc[mt][nt][i] = 0.f;

    w0 = *(const float4*)(W2 + (size_t)kb0 * HH + nq);
    w1 = *(const float4*)(W2 + (size_t)kb1 * HH + nq);
    __syncthreads();   // Pf visible; stage1 Bs reads complete
    *(uint4*)&BS(0)[kb0][nq] = tf32r4(w0);
    *(uint4*)&BS(0)[kb1][nq] = tf32r4(w1);
    __syncthreads();

    cur = 0;
    for (int k0 = 16; k0 < HH; k0 += 16) {
        w0 = *(const float4*)(W2 + (size_t)(k0 + kb0) * HH + nq);
        w1 = *(const float4*)(W2 + (size_t)(k0 + kb1) * HH + nq);
        tile_compute_pf(Pf, BS(cur), acc, k0 - 16, wm, wn, gid, tq);
        *(uint4*)&BS(cur ^ 1)[kb0][nq] = tf32r4(w0);
        *(uint4*)&BS(cur ^ 1)[kb1][nq] = tf32r4(w1);
        __syncthreads();
        cur ^= 1;
    }
    tile_compute_pf(Pf, BS(cur), acc, 112, wm, wn, gid, tq);

    // ---- epilogue 2: ea += 0.5*acc + 0.5*b2 ----
#pragma unroll
    for (int nt = 0; nt < 8; nt++) {
        int col = wn + nt * 8 + tq * 2;
        float bx = b2[col] * 0.5f, by = b2[col + 1] * 0.5f;
#pragma unroll
        for (int mt = 0; mt < 2; mt++) {
            int r0 = m0 + wm + mt * 16 + gid;
            int r1 = r0 + 8;
            {
                float2 c = *(const float2*)(g_ea + (size_t)r0 * HH + col);
                float2 o = make_float2(acc[mt][nt][0] * 0.5f + bx + c.x,
                                       acc[mt][nt][1] * 0.5f + by + c.y);
                *(float2*)(g_ea + (size_t)r0 * HH + col) = o;
            }
            {
                float2 c = *(const float2*)(g_ea + (size_t)r1 * HH + col);
                float2 o = make_float2(acc[mt][nt][2] * 0.5f + bx + c.x,
                                       acc[mt][nt][3] * 0.5f + by + c.y);
                *(float2*)(g_ea + (size_t)r1 * HH + col) = o;
            }
        }
    }
}

// ---------------- fused post+lin on tensor cores (pipelined) ------------------
__global__ __launch_bounds__(256, 2) void k_post_tc(
    const float* __restrict__ Wf, const float* __restrict__ b2p)
{
    __shared__ unsigned As[2][128][20];
    __shared__ unsigned Bs[2][16][136];
    const int t = threadIdx.x;
    const int m0 = blockIdx.x * 128;
    const int warp = t >> 5, lane = t & 31;
    const int gid = lane >> 2, tq = lane & 3;
    const int wm = (warp >> 1) * 32, wn = (warp & 1) * 64;
    const int K = 13 * HH;

    const int rowA0 = t >> 2, rowA1 = 64 + (t >> 2);
    const int kq = (t & 3) * 4;
    const int kb0 = t >> 5, kb1 = 8 + (t >> 5);
    const int nq = (t & 31) * 4;
    const int gr0 = m0 + rowA0, gr1 = m0 + rowA1;
    const bool v0 = gr0 < NN, v1 = gr1 < NN;
    const float amp0 = v0 ? g_amp[gr0] : 0.f, att0 = v0 ? g_att[gr0] : 0.f;
    const float amp1 = v1 ? g_amp[gr1] : 0.f, att1 = v1 ? g_att[gr1] : 0.f;

    float acc[2][8][4];
#pragma unroll
    for (int mt = 0; mt < 2; mt++)
#pragma unroll
        for (int nt = 0; nt < 8; nt++)
#pragma unroll
            for (int i = 0; i < 4; i++) acc[mt][nt][i] = 0.f;

    auto loadA = [&](int gr, bool valid, float amp, float att, int kg) -> float4 {
        if (!valid) return make_float4(0.f, 0.f, 0.f, 0.f);
        if (kg < HH) return *(const float4*)(g_x + (size_t)gr * HH + kg);
        int kk = kg - HH;
        int sec = kk >> 9, j = kk & 511;
        float4 av = *(const float4*)(g_agg + (size_t)gr * 512 + j);
        if (sec != 0) {
            float s = (sec == 1) ? amp : att;
            av.x *= s; av.y *= s; av.z *= s; av.w *= s;
        }
        return av;
    };

    float4 a0 = loadA(gr0, v0, amp0, att0, kq);
    float4 a1 = loadA(gr1, v1, amp1, att1, kq);
    float4 b0 = *(const float4*)(Wf + (size_t)kb0 * HH + nq);
    float4 b1 = *(const float4*)(Wf + (size_t)kb1 * HH + nq);
    *(uint4*)&As[0][rowA0][kq] = tf32r4(a0);
    *(uint4*)&As[0][rowA1][kq] = tf32r4(a1);
    *(uint4*)&Bs[0][kb0][nq] = tf32r4(b0);
    *(uint4*)&Bs[0][kb1][nq] = tf32r4(b1);
    __syncthreads();

    int cur = 0;
    for (int k0 = 16; k0 < K; k0 += 16) {
        a0 = loadA(gr0, v0, amp0, att0, k0 + kq);
        a1 = loadA(gr1, v1, amp1, att1, k0 + kq);
        b0 = *(const float4*)(Wf + (size_t)(k0 + kb0) * HH + nq);
        b1 = *(const float4*)(Wf + (size_t)(k0 + kb1) * HH + nq);
        tile_compute(As[cur], Bs[cur], acc, wm, wn, gid, tq);
        *(uint4*)&As[cur ^ 1][rowA0][kq] = tf32r4(a0);
        *(uint4*)&As[cur ^ 1][rowA1][kq] = tf32r4(a1);
        *(uint4*)&Bs[cur ^ 1][kb0][nq] = tf32r4(b0);
        *(uint4*)&Bs[cur ^ 1][kb1][nq] = tf32r4(b1);
        __syncthreads();
        cur ^= 1;
    }
    tile_compute(As[cur], Bs[cur], acc, wm, wn, gid, tq);

#pragma unroll
    for (int nt = 0; nt < 8; nt++) {
        int col = wn + nt * 8 + tq * 2;
        float bx = b2p[col], by = b2p[col + 1];
#pragma unroll
        for (int mt = 0; mt < 2; mt++) {
            int r0 = m0 + wm + mt * 16 + gid;
            int r1 = r0 + 8;
            if (r0 < NN) {
                float2 o = make_float2(acc[mt][nt][0] + bx, acc[mt][nt][1] + by);
                *(float2*)(g_n1 + (size_t)r0 * HH + col) = o;
            }
            if (r1 < NN) {
                float2 o = make_float2(acc[mt][nt][2] + bx, acc[mt][nt][3] + by);
                *(float2*)(g_n1 + (size_t)r1 * HH + col) = o;
            }
        }
    }
}

// ---------------- exact fp32 SIMT GEMM, batched over layers (weight folds) ----
__global__ __launch_bounds__(256) void k_gemm_fold(
    const float* __restrict__ A0, const float* __restrict__ B0,
    float* __restrict__ C0, int M, int K,
    size_t strA, size_t strB, size_t strC)
{
    const float* A = A0 + blockIdx.y * strA;
    const float* B = B0 + blockIdx.y * strB;
    float* C = C0 + blockIdx.y * strC;
    __shared__ float As[64][16];
    __shared__ float Bs[16][128];
    const int t = threadIdx.x;
    const int m0 = blockIdx.x * 64;
    const int lane = t & 31;
    const int wrow = (t >> 5) * 8;
    const int col0 = lane * 4;
    const int ar = t >> 2;
    const int ak = (t & 3) * 4;
    const int br = t >> 4;
    const int bc = (t & 15) * 8;

    float acc[8][4];
#pragma unroll
    for (int i = 0; i < 8; i++) { acc[i][0]=0.f; acc[i][1]=0.f; acc[i][2]=0.f; acc[i][3]=0.f; }

    for (int k0 = 0; k0 < K; k0 += 16) {
        float4 av = make_float4(0.f,0.f,0.f,0.f);
        int grow = m0 + ar;
        if (grow < M) av = *(const float4*)(A + (size_t)grow * K + k0 + ak);
        *(float4*)&As[ar][ak] = av;
        *(float4*)&Bs[br][bc]     = *(const float4*)(B + (size_t)(k0 + br) * HH + bc);
        *(float4*)&Bs[br][bc + 4] = *(const float4*)(B + (size_t)(k0 + br) * HH + bc + 4);
        __syncthreads();
#pragma unroll
        for (int k = 0; k < 16; k++) {
            float4 b = *(const float4*)&Bs[k][col0];
#pragma unroll
            for (int i = 0; i < 8; i++) {
                float a = As[wrow + i][k];
                acc[i][0] = fmaf(a, b.x, acc[i][0]);
                acc[i][1] = fmaf(a, b.y, acc[i][1]);
                acc[i][2] = fmaf(a, b.z, acc[i][2]);
                acc[i][3] = fmaf(a, b.w, acc[i][3]);
            }
        }
        __syncthreads();
    }
#pragma unroll
    for (int i = 0; i < 8; i++) {
        int r = m0 + wrow + i;
        if (r < M) {
            float4 o = make_float4(acc[i][0], acc[i][1], acc[i][2], acc[i][3]);
            *(float4*)(C + (size_t)r * HH + col0) = o;
        }
    }
}

// bias folds, all layers in one launch: block = (layer, which)
__global__ void k_vecmat2(
    const float* __restrict__ eenc_b, const float* __restrict__ pre_w,
    const float* __restrict__ pre_b,  const float* __restrict__ post_b,
    const float* __restrict__ lin_w,  const float* __restrict__ lin_b)
{
    int l = blockIdx.x >> 1;
    int which = blockIdx.x & 1;
    int j = threadIdx.x;
    const float* v; const float* W; const float* b0; float* out;
    if (which == 0) {
        v = eenc_b + l * HH;
        W = pre_w + (size_t)l * 384 * HH + 256 * HH;
        b0 = pre_b + l * HH;
        out = g_bias1 + l * HH;
    } else {
        v = post_b + l * HH;
        W = lin_w + (size_t)l * HH * HH;
        b0 = lin_b + l * HH;
        out = g_bias2 + l * HH;
    }
    float s = b0[j];
    for (int k = 0; k < HH; k++) s = fmaf(v[k], W[k * HH + j], s);
    out[j] = s;
}

// ---------------- CSR build ---------------------------------------------------
__global__ void k_zeroi(int* p, int n) {
    int i = blockIdx.x * blockDim.x + threadIdx.x;
    if (i < n) p[i] = 0;
}
__global__ void k_degacc(const int* __restrict__ dst) {
    int i = blockIdx.x * blockDim.x + threadIdx.x;
    if (i < EE) atomicAdd(&g_degi[dst[i]], 1);
}
// scan over degrees + node stats (amp/att) in one pass
__global__ __launch_bounds__(1024) void k_scan1(const float* __restrict__ adl_p) {
    __shared__ int sh[1024];
    int i = blockIdx.x * 1024 + threadIdx.x;
    int v = (i < NN) ? g_degi[i] : 0;
    if (i < NN) {
        float adl = __ldg(adl_p);
        float degc = fmaxf((float)v, 1.0f);
        float lg = logf(degc + 1.0f);
        g_amp[i] = lg / adl;
        g_att[i] = adl / lg;
    }
    sh[threadIdx.x] = v;
    __syncthreads();
    for (int off = 1; off < 1024; off <<= 1) {
        int tv = (threadIdx.x >= off) ? sh[threadIdx.x - off] : 0;
        __syncthreads();
        sh[threadIdx.x] += tv;
        __syncthreads();
    }
    if (i < NN) g_rowptr[i + 1] = sh[threadIdx.x];
    if (threadIdx.x == 1023) g_blocksum[blockIdx.x] = sh[1023];
}
__global__ void k_scan2() {
    if (threadIdx.x == 0) {
        int s = 0;
        for (int b = 0; b < NB; b++) { int v = g_blocksum[b]; g_blocksum[b] = s; s += v; }
    }
}
__global__ __launch_bounds__(1024) void k_scan3() {
    int i = blockIdx.x * 1024 + threadIdx.x;
    if (i < NN) {
        int rp = g_rowptr[i + 1] + g_blocksum[i >> 10];
        g_rowptr[i + 1] = rp;
        if (i + 1 < NN) g_cursor[i + 1] = rp;
    }
    if (i == 0) { g_rowptr[0] = 0; g_cursor[0] = 0; }
}
__global__ void k_scatter(const int* __restrict__ src, const int* __restrict__ dst) {
    int e = blockIdx.x * blockDim.x + threadIdx.x;
    if (e >= EE) return;
    int d = dst[e];
    int p = atomicAdd(&g_cursor[d], 1);
    g_eperm[p] = e;
    g_srcs[p] = src[e];
}

// ---------------- small kernels ----------------------------------------------
// CSR aggregation: one warp per node, registers only, no atomics.
__global__ __launch_bounds__(256) void k_msg_csr(const float* __restrict__ b1) {
    int n = blockIdx.x * 8 + (threadIdx.x >> 5);
    if (n >= NN) return;
    int lane = threadIdx.x & 31;
    int c = lane * 4;
    float4 bb = *(const float4*)(b1 + c);
    float4 xd = *(const float4*)(g_n1 + (size_t)n * HH + c);
    float cx = xd.x + bb.x, cy = xd.y + bb.y, cz = xd.z + bb.z, cw = xd.w + bb.w;
    int beg = g_rowptr[n], end = g_rowptr[n + 1];
    float s1x = 0.f, s1y = 0.f, s1z = 0.f, s1w = 0.f;
    float s2x = 0.f, s2y = 0.f, s2z = 0.f, s2w = 0.f;
    float mnx = INFINITY, mny = INFINITY, mnz = INFINITY, mnw = INFINITY;
    float mxx = -INFINITY, mxy = -INFINITY, mxz = -INFINITY, mxw = -INFINITY;
    for (int i = beg; i < end; i++) {
        int s = __ldg(g_srcs + i);
        float4 b = *(const float4*)(g_n2 + (size_t)s * HH + c);
        float4 w = *(const float4*)(g_eb1 + (size_t)i * HH + c);
        float hx = cx + b.x + w.x;
        float hy = cy + b.y + w.y;
        float hz = cz + b.z + w.z;
        float hw = cw + b.w + w.w;
        s1x += hx; s1y += hy; s1z += hz; s1w += hw;
        s2x = fmaf(hx, hx, s2x); s2y = fmaf(hy, hy, s2y);
        s2z = fmaf(hz, hz, s2z); s2w = fmaf(hw, hw, s2w);
        mnx = fminf(mnx, hx); mny = fminf(mny, hy); mnz = fminf(mnz, hz); mnw = fminf(mnw, hw);
        mxx = fmaxf(mxx, hx); mxy = fmaxf(mxy, hy); mxz = fmaxf(mxz, hz); mxw = fmaxf(mxw, hw);
    }
    int deg = end - beg;
    float dinv = (deg > 0) ? (1.0f / (float)deg) : 1.0f;
    if (deg == 0) {
        s1x = s1y = s1z = s1w = 0.f;
        s2x = s2y = s2z = s2w = 0.f;
        mnx = mny = mnz = mnw = 0.f;
        mxx = mxy = mxz = mxw = 0.f;
    }
    float mex = s1x * dinv, mey = s1y * dinv, mez = s1z * dinv, mew = s1w * dinv;
    float sdx = sqrtf(fmaxf(s2x * dinv - mex * mex, 0.f) + 1e-5f);
    float sdy = sqrtf(fmaxf(s2y * dinv - mey * mey, 0.f) + 1e-5f);
    float sdz = sqrtf(fmaxf(s2z * dinv - mez * mez, 0.f) + 1e-5f);
    float sdw = sqrtf(fmaxf(s2w * dinv - mew * mew, 0.f) + 1e-5f);
    size_t bse = (size_t)n * 512;
    *(float4*)(g_agg + bse + c)       = make_float4(mex, mey, mez, mew);
    *(float4*)(g_agg + bse + 128 + c) = make_float4(mnx, mny, mnz, mnw);
    *(float4*)(g_agg + bse + 256 + c) = make_float4(mxx, mxy, mxz, mxw);
    *(float4*)(g_agg + bse + 384 + c) = make_float4(sdx, sdy, sdz, sdw);
}

__global__ void k_bnzero() {
    int t = threadIdx.x;
    g_bns[t] = 0.f;
    g_bnq[t] = 0.f;
}

__global__ __launch_bounds__(256) void k_bnred() {
    __shared__ float sh[256], shq[256];
    int t = threadIdx.x;
    int col = t & 127;
    int half = t >> 7;
    float s = 0.f, q = 0.f;
    for (int row = blockIdx.x * 2 + half; row < NN; row += gridDim.x * 2) {
        float v = g_n1[(size_t)row * HH + col];
        s += v; q += v * v;
    }
    sh[t] = s; shq[t] = q;
    __syncthreads();
    if (half == 0) {
        atomicAdd(&g_bns[col], s + sh[t + 128]);
        atomicAdd(&g_bnq[col], q + shq[t + 128]);
    }
}

// BN + residual; optionally mirrors the result into `extra` (final output)
__global__ void k_bnapply(const float* __restrict__ gamma, const float* __restrict__ beta,
                          float* __restrict__ extra) {
    int i = blockIdx.x * blockDim.x + threadIdx.x;
    if (i >= NN * HH) return;
    int c = i & 127;
    const float invN = 1.0f / (float)NN;
    float mu = g_bns[c] * invN;
    float var = g_bnq[c] * invN - mu * mu;
    float v = g_n1[i];
    float bn = gamma[c] * (v - mu) * rsqrtf(var + 1e-5f) + beta[c];
    float r = (g_x[i] + fmaxf(bn, 0.f)) * 0.5f;
    g_x[i] = r;
    if (extra) extra[i] = r;
}

// ---------------- host orchestration -----------------------------------------
extern "C" void kernel_launch(void* const* d_in, const int* in_sizes, int n_in,
                              void* d_out, int out_size) {
    const float* x_in   = (const float*)d_in[0];
    const int*   ei     = (const int*)d_in[1];
    const float* eattr  = (const float*)d_in[2];
    const float* pattr  = (const float*)d_in[4];
    const float* nattr  = (const float*)d_in[6];
    const float* adl    = (const float*)d_in[7];
    const float* node_w = (const float*)d_in[8];
    const float* node_b = (const float*)d_in[9];
    const float* edge_w = (const float*)d_in[10];
    const float* edge_b = (const float*)d_in[11];
    const float* eenc_w = (const float*)d_in[12];
    const float* eenc_b = (const float*)d_in[13];
    const float* pre_w  = (const float*)d_in[14];
    const float* pre_b  = (const float*)d_in[15];
    const float* post_w = (const float*)d_in[16];
    const float* post_b = (const float*)d_in[17];
    const float* lin_w  = (const float*)d_in[18];
    const float* lin_b  = (const float*)d_in[19];
    const float* ew1    = (const float*)d_in[20];
    const float* eb1v   = (const float*)d_in[21];
    const float* ew2    = (const float*)d_in[22];
    const float* eb2v   = (const float*)d_in[23];
    const float* bng    = (const float*)d_in[24];
    const float* bnb    = (const float*)d_in[25];
    float* out = (float*)d_out;

    float *p_x, *p_ea, *p_n1, *p_n2, *p_eb1, *p_W3, *p_Wfold, *p_b1, *p_b2;
    int *p_degi, *p_eperm;
    cudaGetSymbolAddress((void**)&p_x, g_x);
    cudaGetSymbolAddress((void**)&p_ea, g_ea);
    cudaGetSymbolAddress((void**)&p_n1, g_n1);
    cudaGetSymbolAddress((void**)&p_n2, g_n2);
    cudaGetSymbolAddress((void**)&p_eb1, g_eb1);
    cudaGetSymbolAddress((void**)&p_W3, g_W3);
    cudaGetSymbolAddress((void**)&p_Wfold, g_Wfold);
    cudaGetSymbolAddress((void**)&p_b1, g_bias1);
    cudaGetSymbolAddress((void**)&p_b2, g_bias2);
    cudaGetSymbolAddress((void**)&p_degi, g_degi);
    cudaGetSymbolAddress((void**)&p_eperm, g_eperm);

    const int* src = ei;
    const int* dst = ei + EE;

    // dynamic-smem opt-in for the fused kernel (idempotent, every call)
    const int SMEM_UPD = (128 * 132 + 2 * 128 * 20 + 2 * 16 * 136) * 4; // 105472
    cudaFuncSetAttribute(k_upd_fused, cudaFuncAttributeMaxDynamicSharedMemorySize, SMEM_UPD);

    auto gemm = [](const float* A, const float* B, const float* bias, float* C,
                   const int* Aidx, int M, int K, float alpha, float bscale) {
        k_gemm_tc<<<(M + 127) / 128, 256>>>(A, B, bias, C, Aidx, M, K, alpha, bscale);
    };

    // ---- CSR build (once) ----
    k_zeroi<<<(NN + 255) / 256, 256>>>(p_degi, NN);
    k_degacc<<<(EE + 255) / 256, 256>>>(dst);
    k_scan1<<<NB, 1024>>>(adl);
    k_scan2<<<1, 32>>>();
    k_scan3<<<NB, 1024>>>();
    k_scatter<<<(EE + 255) / 256, 256>>>(src, dst);

    // ---- weight/bias folds, both layers batched ----
    k_gemm_fold<<<dim3(2, 2), 256>>>(eenc_w, pre_w + 256 * HH, p_W3, HH, HH,
                                     (size_t)HH * HH, (size_t)384 * HH, (size_t)HH * HH);
    k_gemm_fold<<<dim3(26, 2), 256>>>(post_w, lin_w, p_Wfold, 13 * HH, HH,
                                      (size_t)1664 * HH, (size_t)HH * HH, (size_t)1664 * HH);
    k_vecmat2<<<4, 128>>>(eenc_b, pre_w, pre_b, post_b, lin_w, lin_b);

    // ---- embeddings ----
    gemm(x_in, node_w, node_b, p_x, nullptr, NN, 64, 1.f, 1.f);
    gemm(eattr, edge_w, edge_b, p_ea, nullptr, EE, 32, 1.f, 1.f);
    gemm(pattr, edge_w, edge_b, out + (size_t)NN * HH, nullptr, EPP, 32, 1.f, 1.f);
    gemm(nattr, edge_w, edge_b, out + (size_t)NN * HH + (size_t)EPP * HH, nullptr, EPP, 32, 1.f, 1.f);

    for (int l = 0; l < LL; l++) {
        const float* preW = pre_w + (size_t)l * 384 * HH;
        const float* e1W = ew1 + (size_t)l * 384 * HH;
        const float* e2W = ew2 + (size_t)l * HH * HH;
        const bool last = (l == LL - 1);

        // message projections
        gemm(p_x, preW, nullptr, p_n1, nullptr, NN, HH, 1.f, 1.f);            // x@P0 (dst)
        gemm(p_x, preW + 128 * HH, nullptr, p_n2, nullptr, NN, HH, 1.f, 1.f); // x@P1 (src)
        gemm(p_ea, p_W3 + (size_t)l * HH * HH, nullptr, p_eb1, p_eperm, EE, HH, 1.f, 1.f);

        // aggregate (no atomics)
        k_msg_csr<<<(NN + 7) / 8, 256>>>(p_b1 + l * HH);

        // node update: fused post+lin, then BN + residual
        k_post_tc<<<(NN + 127) / 128, 256>>>(p_Wfold + (size_t)l * 1664 * HH, p_b2 + l * HH);
        k_bnzero<<<1, 128>>>();
        k_bnred<<<256, 256>>>();
        k_bnapply<<<(NN * HH + 255) / 256, 256>>>(bng + l * HH, bnb + l * HH,
                                                  last ? out : nullptr);

        // edge update — DEAD on the last layer; otherwise fully fused
        if (!last) {
            gemm(p_x, e1W, nullptr, p_n1, nullptr, NN, HH, 1.f, 1.f);            // x@U0 (src)
            gemm(p_x, e1W + 128 * HH, nullptr, p_n2, nullptr, NN, HH, 1.f, 1.f); // x@U1 (dst)
            k_upd_fused<<<EE / 128, 256, SMEM_UPD>>>(src, dst, e1W + 256 * HH,
                                                     eb1v + l * HH, e2W, eb2v + l * HH);
        }
    }
}